// round 6
// baseline (speedup 1.0000x reference)
#include <cuda_runtime.h>
#include <cuda_bf16.h>

// ---------------------------------------------------------------------------
// StatePerturbationEncoder: gather -> [GEMM + GELU + BN]x3 -> GEMM + GELU
// BN folded into next layer's weights: (x*a + c)@W = x@(diag(a)W) + c@W
// GEMMs in split-bf16 (hi/lo) mma.sync with fp32 accumulate (~fp32 accuracy).
// R5 fix: B-tile smem loader used uint2 (4 bf16) per 8-element slot, leaving
// half the tile uninitialized -> nan. Now uint4 (8 bf16) with aligned smem.
// ---------------------------------------------------------------------------

#define NROWS 32768      // B*C
#define DIMD  256
#define NRB   256        // row blocks (NROWS/128)
#define EPSF  1e-5f

// ----- scratch (static device globals; allocation-free at runtime) ---------
__device__ __align__(256) static float g_y1[NROWS * DIMD];
__device__ __align__(256) static float g_y2[NROWS * DIMD];
__device__ __align__(256) static float g_ps[NRB * DIMD];   // partial col sums
__device__ __align__(256) static float g_pq[NRB * DIMD];   // partial col sumsq
__device__ __align__(256) static __nv_bfloat16 g_w1h[DIMD*DIMD], g_w1l[DIMD*DIMD];
__device__ __align__(256) static __nv_bfloat16 g_w2h[DIMD*DIMD], g_w2l[DIMD*DIMD];
__device__ __align__(256) static __nv_bfloat16 g_w3h[DIMD*DIMD], g_w3l[DIMD*DIMD];
__device__ __align__(256) static __nv_bfloat16 g_w4h[DIMD*DIMD], g_w4l[DIMD*DIMD];
__device__ __align__(256) static float g_a[DIMD], g_c[DIMD];
__device__ __align__(256) static float g_bp[3][DIMD];      // folded biases for layers 2..4

// ----- helpers -------------------------------------------------------------
__device__ __forceinline__ void split_bf16(float x, __nv_bfloat16& h, __nv_bfloat16& l) {
    h = __float2bfloat16(x);
    l = __float2bfloat16(x - __bfloat162float(h));
}

__device__ __forceinline__ float gelu_exact(float x) {
    return x * normcdff(x);   // x * Phi(x), matches jax.nn.gelu(approximate=False)
}

__device__ __forceinline__ void mma_bf16(float* d, const unsigned* a, const unsigned* b) {
    asm volatile(
        "mma.sync.aligned.m16n8k16.row.col.f32.bf16.bf16.f32 "
        "{%0,%1,%2,%3}, {%4,%5,%6,%7}, {%8,%9}, {%0,%1,%2,%3};\n"
        : "+f"(d[0]), "+f"(d[1]), "+f"(d[2]), "+f"(d[3])
        : "r"(a[0]), "r"(a[1]), "r"(a[2]), "r"(a[3]), "r"(b[0]), "r"(b[1]));
}

// ----- W1 transpose + split (layer-1 weights, no BN folding) ---------------
__global__ void winit_kernel(const float* __restrict__ W1) {
    int j = blockIdx.x, k = threadIdx.x;       // j = out col, k = in dim
    __nv_bfloat16 h, l;
    split_bf16(W1[k * DIMD + j], h, l);
    g_w1h[j * DIMD + k] = h;                   // stored [n][k] (transposed)
    g_w1l[j * DIMD + k] = l;
}

// ----- finalize BN stats: a = g*rsqrt(var+eps), c = be - mu*a --------------
__global__ void fin_kernel(const float* __restrict__ gam, const float* __restrict__ bet) {
    int t = threadIdx.x;
    float s = 0.f, q = 0.f;
    #pragma unroll 8
    for (int rb = 0; rb < NRB; ++rb) {         // fixed order -> deterministic
        s += g_ps[rb * DIMD + t];
        q += g_pq[rb * DIMD + t];
    }
    const float invn = 1.0f / (float)NROWS;
    float mu  = s * invn;
    float var = q * invn - mu * mu;
    if (var < 0.f) var = 0.f;                  // numerical guard
    float ai  = gam[t] * rsqrtf(var + EPSF);
    g_a[t] = ai;
    g_c[t] = bet[t] - mu * ai;
}

// ----- fold BN into next layer: W' = diag(a)W (transposed hi/lo), b' = b + c@W
__global__ void wprep_kernel(const float* __restrict__ W, const float* __restrict__ b,
                             int wsel, int bidx) {
    int j = blockIdx.x, k = threadIdx.x;
    float w  = W[k * DIMD + j];
    float wp = g_a[k] * w;
    __nv_bfloat16 h, l;
    split_bf16(wp, h, l);
    __nv_bfloat16 *Wh, *Wl;
    switch (wsel) {
        case 1:  Wh = g_w2h; Wl = g_w2l; break;
        case 2:  Wh = g_w3h; Wl = g_w3l; break;
        default: Wh = g_w4h; Wl = g_w4l; break;
    }
    Wh[j * DIMD + k] = h;
    Wl[j * DIMD + k] = l;

    __shared__ float red[DIMD];
    red[k] = g_c[k] * w;
    __syncthreads();
    #pragma unroll
    for (int off = 128; off > 0; off >>= 1) {  // fixed-order tree reduce
        if (k < off) red[k] += red[k + off];
        __syncthreads();
    }
    if (k == 0) g_bp[bidx][j] = b[j] + red[0];
}

// ----- fused GEMM: Y = gelu(X @ W'^T(hi/lo) + bias), + per-column stats ----
// block tile 128x128, K-chunks of 32, 8 warps (4M x 2N), warp tile 32x64
__global__ __launch_bounds__(256, 1)
void gemm_kernel(int xsel, int ysel, float* __restrict__ dout,
                 const int* __restrict__ ids, const float* __restrict__ table,
                 int wsel, const float* __restrict__ bias_ext, int bidx,
                 int do_stats) {
    const float* X = (xsel == 1) ? g_y1 : (xsel == 2) ? g_y2 : nullptr;
    float* Y = (ysel == 1) ? g_y1 : (ysel == 2) ? g_y2 : dout;
    const __nv_bfloat16 *Wh, *Wl;
    switch (wsel) {
        case 0:  Wh = g_w1h; Wl = g_w1l; break;
        case 1:  Wh = g_w2h; Wl = g_w2l; break;
        case 2:  Wh = g_w3h; Wl = g_w3l; break;
        default: Wh = g_w4h; Wl = g_w4l; break;
    }
    const float* bias = (bidx >= 0) ? g_bp[bidx] : bias_ext;

    // stride 40 bf16 = 80 B: odd multiple of 16 B per row -> uint4-aligned,
    // and 8-element phase shift per row avoids ldmatrix-free LDS conflicts.
    __shared__ __align__(16) __nv_bfloat16 Ah[128][40], Al[128][40];
    __shared__ __align__(16) __nv_bfloat16 Bh[128][40], Bl[128][40];
    __shared__ const float* rowp[128];
    __shared__ float bias_s[128];
    __shared__ float csum[4][128], csq[4][128];

    const int tid  = threadIdx.x;
    const int rb   = blockIdx.y, cb = blockIdx.x;
    const int warp = tid >> 5, lane = tid & 31;
    const int wm   = warp & 3,  wn  = warp >> 2;
    const int g8   = lane >> 2, tq  = lane & 3;

    if (tid < 128) {
        int r = rb * 128 + tid;
        rowp[tid]   = (xsel == 0) ? (table + (size_t)ids[r] * DIMD)
                                  : (X + (size_t)r * DIMD);
        bias_s[tid] = bias[cb * 128 + tid];
    }

    float acc[2][8][4];
    #pragma unroll
    for (int mt = 0; mt < 2; ++mt)
        #pragma unroll
        for (int nt = 0; nt < 8; ++nt)
            #pragma unroll
            for (int e = 0; e < 4; ++e) acc[mt][nt][e] = 0.f;

    const __nv_bfloat16* WhBase = Wh + (size_t)(cb * 128) * DIMD;
    const __nv_bfloat16* WlBase = Wl + (size_t)(cb * 128) * DIMD;

    for (int kc = 0; kc < 8; ++kc) {
        __syncthreads();   // protect smem reuse (and rowp/bias_s on iter 0)

        // A tile: 128x32 fp32 -> split bf16 hi/lo (4 float4 per thread)
        #pragma unroll
        for (int i = 0; i < 4; ++i) {
            int idx = tid + i * 256;
            int row = idx >> 3, seg = idx & 7;
            float4 v = *(const float4*)(rowp[row] + kc * 32 + seg * 4);
            __nv_bfloat16 h0, h1, h2, h3, l0, l1, l2, l3;
            split_bf16(v.x, h0, l0); split_bf16(v.y, h1, l1);
            split_bf16(v.z, h2, l2); split_bf16(v.w, h3, l3);
            __nv_bfloat162 p;
            p.x = h0; p.y = h1; *(__nv_bfloat162*)&Ah[row][seg * 4]     = p;
            p.x = h2; p.y = h3; *(__nv_bfloat162*)&Ah[row][seg * 4 + 2] = p;
            p.x = l0; p.y = l1; *(__nv_bfloat162*)&Al[row][seg * 4]     = p;
            p.x = l2; p.y = l3; *(__nv_bfloat162*)&Al[row][seg * 4 + 2] = p;
        }
        // B tile: 128x32 bf16, hi + lo. uint4 = 8 bf16 per slot (FIXED):
        // 2 iters x 256 threads x 8 bf16 = 4096 = 128x32 elements each.
        #pragma unroll
        for (int i = 0; i < 2; ++i) {
            int idx = tid + i * 256;
            int row = idx >> 2, s2 = idx & 3;
            *(uint4*)&Bh[row][s2 * 8] =
                *(const uint4*)(WhBase + (size_t)row * DIMD + kc * 32 + s2 * 8);
            *(uint4*)&Bl[row][s2 * 8] =
                *(const uint4*)(WlBase + (size_t)row * DIMD + kc * 32 + s2 * 8);
        }
        __syncthreads();

        #pragma unroll
        for (int ks = 0; ks < 2; ++ks) {
            const int kb = ks * 16;
            unsigned ah[2][4], al[2][4];
            #pragma unroll
            for (int mt = 0; mt < 2; ++mt) {
                int r = wm * 32 + mt * 16 + g8;
                ah[mt][0] = *(const unsigned*)&Ah[r    ][kb + tq * 2];
                ah[mt][1] = *(const unsigned*)&Ah[r + 8][kb + tq * 2];
                ah[mt][2] = *(const unsigned*)&Ah[r    ][kb + tq * 2 + 8];
                ah[mt][3] = *(const unsigned*)&Ah[r + 8][kb + tq * 2 + 8];
                al[mt][0] = *(const unsigned*)&Al[r    ][kb + tq * 2];
                al[mt][1] = *(const unsigned*)&Al[r + 8][kb + tq * 2];
                al[mt][2] = *(const unsigned*)&Al[r    ][kb + tq * 2 + 8];
                al[mt][3] = *(const unsigned*)&Al[r + 8][kb + tq * 2 + 8];
            }
            unsigned bh[8][2], bl[8][2];
            #pragma unroll
            for (int nt = 0; nt < 8; ++nt) {
                int cn = wn * 64 + nt * 8 + g8;
                bh[nt][0] = *(const unsigned*)&Bh[cn][kb + tq * 2];
                bh[nt][1] = *(const unsigned*)&Bh[cn][kb + tq * 2 + 8];
                bl[nt][0] = *(const unsigned*)&Bl[cn][kb + tq * 2];
                bl[nt][1] = *(const unsigned*)&Bl[cn][kb + tq * 2 + 8];
            }
            #pragma unroll
            for (int mt = 0; mt < 2; ++mt)
                #pragma unroll
                for (int nt = 0; nt < 8; ++nt) {
                    mma_bf16(acc[mt][nt], ah[mt], bh[nt]);  // hi*hi
                    mma_bf16(acc[mt][nt], ah[mt], bl[nt]);  // hi*lo
                    mma_bf16(acc[mt][nt], al[mt], bh[nt]);  // lo*hi
                }
        }
    }

    // ---- epilogue: bias + exact GELU ----
    #pragma unroll
    for (int mt = 0; mt < 2; ++mt)
        #pragma unroll
        for (int nt = 0; nt < 8; ++nt) {
            int c0 = wn * 64 + nt * 8 + tq * 2;
            float b0 = bias_s[c0], b1 = bias_s[c0 + 1];
            acc[mt][nt][0] = gelu_exact(acc[mt][nt][0] + b0);
            acc[mt][nt][1] = gelu_exact(acc[mt][nt][1] + b1);
            acc[mt][nt][2] = gelu_exact(acc[mt][nt][2] + b0);
            acc[mt][nt][3] = gelu_exact(acc[mt][nt][3] + b1);
        }

    // ---- store Y ----
    #pragma unroll
    for (int mt = 0; mt < 2; ++mt)
        #pragma unroll
        for (int nt = 0; nt < 8; ++nt) {
            int r = rb * 128 + wm * 32 + mt * 16 + g8;
            int c = cb * 128 + wn * 64 + nt * 8 + tq * 2;
            *(float2*)&Y[(size_t)r * DIMD + c]       = make_float2(acc[mt][nt][0], acc[mt][nt][1]);
            *(float2*)&Y[(size_t)(r + 8) * DIMD + c] = make_float2(acc[mt][nt][2], acc[mt][nt][3]);
        }

    // ---- fused per-column BN stats (deterministic: no float atomics) ----
    if (do_stats) {
        #pragma unroll
        for (int nt = 0; nt < 8; ++nt) {
            float s0 = acc[0][nt][0] + acc[0][nt][2] + acc[1][nt][0] + acc[1][nt][2];
            float s1 = acc[0][nt][1] + acc[0][nt][3] + acc[1][nt][1] + acc[1][nt][3];
            float q0 = acc[0][nt][0]*acc[0][nt][0] + acc[0][nt][2]*acc[0][nt][2]
                     + acc[1][nt][0]*acc[1][nt][0] + acc[1][nt][2]*acc[1][nt][2];
            float q1 = acc[0][nt][1]*acc[0][nt][1] + acc[0][nt][3]*acc[0][nt][3]
                     + acc[1][nt][1]*acc[1][nt][1] + acc[1][nt][3]*acc[1][nt][3];
            #pragma unroll
            for (int off = 4; off < 32; off <<= 1) {   // reduce over row-groups (g8)
                s0 += __shfl_xor_sync(0xffffffffu, s0, off);
                s1 += __shfl_xor_sync(0xffffffffu, s1, off);
                q0 += __shfl_xor_sync(0xffffffffu, q0, off);
                q1 += __shfl_xor_sync(0xffffffffu, q1, off);
            }
            if (lane < 4) {
                int cl = wn * 64 + nt * 8 + lane * 2;  // lane==tq here
                csum[wm][cl] = s0; csum[wm][cl + 1] = s1;
                csq [wm][cl] = q0; csq [wm][cl + 1] = q1;
            }
        }
        __syncthreads();
        if (tid < 128) {
            float S = csum[0][tid] + csum[1][tid] + csum[2][tid] + csum[3][tid];
            float Q = csq [0][tid] + csq [1][tid] + csq [2][tid] + csq [3][tid];
            g_ps[rb * DIMD + cb * 128 + tid] = S;
            g_pq[rb * DIMD + cb * 128 + tid] = Q;
        }
    }
}

// ---------------------------------------------------------------------------
extern "C" void kernel_launch(void* const* d_in, const int* in_sizes, int n_in,
                              void* d_out, int out_size) {
    (void)in_sizes; (void)n_in; (void)out_size;
    const int*   ids   = (const int*)  d_in[0];
    const float* table = (const float*)d_in[1];
    const float* W1 = (const float*)d_in[2],  *b1 = (const float*)d_in[3];
    const float* W2 = (const float*)d_in[4],  *b2 = (const float*)d_in[5];
    const float* W3 = (const float*)d_in[6],  *b3 = (const float*)d_in[7];
    const float* W4 = (const float*)d_in[8],  *b4 = (const float*)d_in[9];
    const float* g1 = (const float*)d_in[10], *be1 = (const float*)d_in[11];
    const float* g2 = (const float*)d_in[12], *be2 = (const float*)d_in[13];
    const float* g3 = (const float*)d_in[14], *be3 = (const float*)d_in[15];
    float* out = (float*)d_out;

    dim3 grid(2, NRB), blk(256);

    winit_kernel<<<DIMD, DIMD>>>(W1);
    // layer 1: gather -> gelu(emb @ W1 + b1) -> y1 (+stats)
    gemm_kernel<<<grid, blk>>>(0, 1, nullptr, ids, table, 0, b1, -1, 1);
    fin_kernel<<<1, DIMD>>>(g1, be1);
    wprep_kernel<<<DIMD, DIMD>>>(W2, b2, 1, 0);
    // layer 2: gelu(bn1(y1) @ W2 + b2) -> y2 (+stats)
    gemm_kernel<<<grid, blk>>>(1, 2, nullptr, ids, table, 1, nullptr, 0, 1);
    fin_kernel<<<1, DIMD>>>(g2, be2);
    wprep_kernel<<<DIMD, DIMD>>>(W3, b3, 2, 1);
    // layer 3: -> y1 (+stats)
    gemm_kernel<<<grid, blk>>>(2, 1, nullptr, ids, table, 2, nullptr, 1, 1);
    fin_kernel<<<1, DIMD>>>(g3, be3);
    wprep_kernel<<<DIMD, DIMD>>>(W4, b4, 3, 2);
    // layer 4: -> d_out (no stats)
    gemm_kernel<<<grid, blk>>>(1, 3, out, ids, table, 3, nullptr, 2, 0);
}

// round 7
// speedup vs baseline: 1.3055x; 1.3055x over previous
#include <cuda_runtime.h>
#include <cuda_bf16.h>

// ---------------------------------------------------------------------------
// StatePerturbationEncoder: gather -> [GEMM + GELU + BN]x3 -> GEMM + GELU
// BN folded into next layer's weights: (x*a + c)@W = x@(diag(a)W) + c@W
// GEMMs in split-bf16 (hi/lo) mma.sync with fp32 accumulate (~fp32 accuracy).
// R7: activations stored PRE-SPLIT as bf16 hi/lo (split once in epilogue, not
// per k-chunk), gather moved to a tiny pre-kernel, and the GEMM mainloop is a
// 3-stage cp.async pipeline (loads overlap MMA). Math identical to R6.
// ---------------------------------------------------------------------------

#define NROWS 32768      // B*C
#define DIMD  256
#define NRB   256        // row blocks (NROWS/128)
#define EPSF  1e-5f

#define STAGES    3
#define TILE_ROWS 128
#define TILE_K    32
#define LDS_STRIDE 40                  // 32 + 8 pad; 80B rows keep uint4 alignment
#define ARR_ELEMS (TILE_ROWS * LDS_STRIDE)       // 5120 bf16 per array
#define STG_ELEMS (4 * ARR_ELEMS)                // Ah, Al, Bh, Bl
#define SMEM_BYTES (STAGES * STG_ELEMS * 2)      // 122880 B dynamic smem

// ----- scratch (static device globals; allocation-free at runtime) ---------
__device__ __align__(256) static __nv_bfloat16 g_x0h[NROWS*DIMD], g_x0l[NROWS*DIMD];
__device__ __align__(256) static __nv_bfloat16 g_x1h[NROWS*DIMD], g_x1l[NROWS*DIMD];
__device__ __align__(256) static __nv_bfloat16 g_x2h[NROWS*DIMD], g_x2l[NROWS*DIMD];
__device__ __align__(256) static float g_ps[NRB * DIMD];   // partial col sums
__device__ __align__(256) static float g_pq[NRB * DIMD];   // partial col sumsq
__device__ __align__(256) static __nv_bfloat16 g_w1h[DIMD*DIMD], g_w1l[DIMD*DIMD];
__device__ __align__(256) static __nv_bfloat16 g_w2h[DIMD*DIMD], g_w2l[DIMD*DIMD];
__device__ __align__(256) static __nv_bfloat16 g_w3h[DIMD*DIMD], g_w3l[DIMD*DIMD];
__device__ __align__(256) static __nv_bfloat16 g_w4h[DIMD*DIMD], g_w4l[DIMD*DIMD];
__device__ __align__(256) static float g_a[DIMD], g_c[DIMD];
__device__ __align__(256) static float g_bp[3][DIMD];      // folded biases, layers 2..4

// ----- helpers -------------------------------------------------------------
__device__ __forceinline__ void split_bf16(float x, __nv_bfloat16& h, __nv_bfloat16& l) {
    h = __float2bfloat16(x);
    l = __float2bfloat16(x - __bfloat162float(h));
}

__device__ __forceinline__ float gelu_exact(float x) {
    return x * normcdff(x);   // x * Phi(x), matches jax.nn.gelu(approximate=False)
}

__device__ __forceinline__ void mma_bf16(float* d, const unsigned* a, const unsigned* b) {
    asm volatile(
        "mma.sync.aligned.m16n8k16.row.col.f32.bf16.bf16.f32 "
        "{%0,%1,%2,%3}, {%4,%5,%6,%7}, {%8,%9}, {%0,%1,%2,%3};\n"
        : "+f"(d[0]), "+f"(d[1]), "+f"(d[2]), "+f"(d[3])
        : "r"(a[0]), "r"(a[1]), "r"(a[2]), "r"(a[3]), "r"(b[0]), "r"(b[1]));
}

__device__ __forceinline__ void cp_async16(__nv_bfloat16* sdst, const __nv_bfloat16* gsrc) {
    unsigned sa = (unsigned)__cvta_generic_to_shared(sdst);
    asm volatile("cp.async.cg.shared.global [%0], [%1], 16;\n" :: "r"(sa), "l"(gsrc) : "memory");
}

// ----- gather + split: x0 = split(table[ids]) -------------------------------
__global__ void gather_kernel(const int* __restrict__ ids, const float* __restrict__ table) {
    int t = blockIdx.x * blockDim.x + threadIdx.x;     // 262144 threads
    #pragma unroll
    for (int i = 0; i < 8; ++i) {
        int c   = t + (i << 18);                       // float4 chunk id
        int row = c >> 6;                              // 64 float4 per row
        int seg = (c & 63) << 2;                       // float offset in row
        const float* src = table + (size_t)ids[row] * DIMD + seg;
        float4 v = *(const float4*)src;
        __nv_bfloat16 h0,l0,h1,l1,h2,l2,h3,l3;
        split_bf16(v.x, h0, l0); split_bf16(v.y, h1, l1);
        split_bf16(v.z, h2, l2); split_bf16(v.w, h3, l3);
        size_t off = (size_t)row * DIMD + seg;
        __nv_bfloat162 p;
        p.x = h0; p.y = h1; *(__nv_bfloat162*)(g_x0h + off)     = p;
        p.x = h2; p.y = h3; *(__nv_bfloat162*)(g_x0h + off + 2) = p;
        p.x = l0; p.y = l1; *(__nv_bfloat162*)(g_x0l + off)     = p;
        p.x = l2; p.y = l3; *(__nv_bfloat162*)(g_x0l + off + 2) = p;
    }
}

// ----- W1 transpose + split (layer-1 weights, no BN folding) ---------------
__global__ void winit_kernel(const float* __restrict__ W1) {
    int j = blockIdx.x, k = threadIdx.x;       // j = out col, k = in dim
    __nv_bfloat16 h, l;
    split_bf16(W1[k * DIMD + j], h, l);
    g_w1h[j * DIMD + k] = h;                   // stored [n][k] (transposed)
    g_w1l[j * DIMD + k] = l;
}

// ----- finalize BN stats: a = g*rsqrt(var+eps), c = be - mu*a --------------
__global__ void fin_kernel(const float* __restrict__ gam, const float* __restrict__ bet) {
    int t = threadIdx.x;
    float s = 0.f, q = 0.f;
    #pragma unroll 8
    for (int rb = 0; rb < NRB; ++rb) {         // fixed order -> deterministic
        s += g_ps[rb * DIMD + t];
        q += g_pq[rb * DIMD + t];
    }
    const float invn = 1.0f / (float)NROWS;
    float mu  = s * invn;
    float var = q * invn - mu * mu;
    if (var < 0.f) var = 0.f;                  // numerical guard
    float ai  = gam[t] * rsqrtf(var + EPSF);
    g_a[t] = ai;
    g_c[t] = bet[t] - mu * ai;
}

// ----- fold BN into next layer: W' = diag(a)W (transposed hi/lo), b' = b + c@W
__global__ void wprep_kernel(const float* __restrict__ W, const float* __restrict__ b,
                             int wsel, int bidx) {
    int j = blockIdx.x, k = threadIdx.x;
    float w  = W[k * DIMD + j];
    float wp = g_a[k] * w;
    __nv_bfloat16 h, l;
    split_bf16(wp, h, l);
    __nv_bfloat16 *Wh, *Wl;
    switch (wsel) {
        case 1:  Wh = g_w2h; Wl = g_w2l; break;
        case 2:  Wh = g_w3h; Wl = g_w3l; break;
        default: Wh = g_w4h; Wl = g_w4l; break;
    }
    Wh[j * DIMD + k] = h;
    Wl[j * DIMD + k] = l;

    __shared__ float red[DIMD];
    red[k] = g_c[k] * w;
    __syncthreads();
    #pragma unroll
    for (int off = 128; off > 0; off >>= 1) {  // fixed-order tree reduce
        if (k < off) red[k] += red[k + off];
        __syncthreads();
    }
    if (k == 0) g_bp[bidx][j] = b[j] + red[0];
}

// ----- fused GEMM: Y = gelu(X @ W'^T(hi/lo) + bias), + per-column stats ----
// block tile 128x128, K-chunks of 32, 8 warps (4M x 2N), warp tile 32x64
// 3-stage cp.async pipeline; A pre-split bf16 (no in-loop conversion).
__global__ __launch_bounds__(256, 1)
void gemm_kernel(int xsel, int ysel, float* __restrict__ dout,
                 int wsel, const float* __restrict__ bias_ext, int bidx,
                 int do_stats) {
    const __nv_bfloat16 *Xh, *Xl;
    if      (xsel == 0) { Xh = g_x0h; Xl = g_x0l; }
    else if (xsel == 1) { Xh = g_x1h; Xl = g_x1l; }
    else                { Xh = g_x2h; Xl = g_x2l; }
    __nv_bfloat16 *Yh = nullptr, *Yl = nullptr;
    if      (ysel == 1) { Yh = g_x1h; Yl = g_x1l; }
    else if (ysel == 2) { Yh = g_x2h; Yl = g_x2l; }
    const __nv_bfloat16 *Wh, *Wl;
    switch (wsel) {
        case 0:  Wh = g_w1h; Wl = g_w1l; break;
        case 1:  Wh = g_w2h; Wl = g_w2l; break;
        case 2:  Wh = g_w3h; Wl = g_w3l; break;
        default: Wh = g_w4h; Wl = g_w4l; break;
    }
    const float* bias = (bidx >= 0) ? g_bp[bidx] : bias_ext;

    extern __shared__ __align__(16) __nv_bfloat16 smem[];   // [STAGES][Ah|Al|Bh|Bl][128][40]
    __shared__ float bias_s[128];
    __shared__ float csum[4][128], csq[4][128];

    const int tid  = threadIdx.x;
    const int rb   = blockIdx.y, cb = blockIdx.x;
    const int warp = tid >> 5, lane = tid & 31;
    const int wm   = warp & 3,  wn  = warp >> 2;
    const int g8   = lane >> 2, tq  = lane & 3;

    if (tid < 128) bias_s[tid] = bias[cb * 128 + tid];

    const __nv_bfloat16* Xhb = Xh + (size_t)(rb * 128) * DIMD;
    const __nv_bfloat16* Xlb = Xl + (size_t)(rb * 128) * DIMD;
    const __nv_bfloat16* Whb = Wh + (size_t)(cb * 128) * DIMD;
    const __nv_bfloat16* Wlb = Wl + (size_t)(cb * 128) * DIMD;

    // per-thread load geometry: slot = (row, 16B segment); thread covers rows
    // r0 and r0+64 of each of the 4 arrays (8 cp.async per stage).
    const int r0 = tid >> 2;
    const int s8 = (tid & 3) * 8;            // bf16 element offset within row

    auto load_stage = [&](int st, int kc) {
        __nv_bfloat16* base = smem + st * STG_ELEMS;
        const int koff = kc * TILE_K + s8;
        const int r1 = r0 + 64;
        cp_async16(base                 + r0 * LDS_STRIDE + s8, Xhb + (size_t)r0 * DIMD + koff);
        cp_async16(base +     ARR_ELEMS + r0 * LDS_STRIDE + s8, Xlb + (size_t)r0 * DIMD + koff);
        cp_async16(base + 2 * ARR_ELEMS + r0 * LDS_STRIDE + s8, Whb + (size_t)r0 * DIMD + koff);
        cp_async16(base + 3 * ARR_ELEMS + r0 * LDS_STRIDE + s8, Wlb + (size_t)r0 * DIMD + koff);
        cp_async16(base                 + r1 * LDS_STRIDE + s8, Xhb + (size_t)r1 * DIMD + koff);
        cp_async16(base +     ARR_ELEMS + r1 * LDS_STRIDE + s8, Xlb + (size_t)r1 * DIMD + koff);
        cp_async16(base + 2 * ARR_ELEMS + r1 * LDS_STRIDE + s8, Whb + (size_t)r1 * DIMD + koff);
        cp_async16(base + 3 * ARR_ELEMS + r1 * LDS_STRIDE + s8, Wlb + (size_t)r1 * DIMD + koff);
    };

    float acc[2][8][4];
    #pragma unroll
    for (int mt = 0; mt < 2; ++mt)
        #pragma unroll
        for (int nt = 0; nt < 8; ++nt)
            #pragma unroll
            for (int e = 0; e < 4; ++e) acc[mt][nt][e] = 0.f;

    // pipeline prologue: stages 0,1 in flight
    load_stage(0, 0);
    asm volatile("cp.async.commit_group;\n" ::: "memory");
    load_stage(1, 1);
    asm volatile("cp.async.commit_group;\n" ::: "memory");

    for (int kc = 0; kc < 8; ++kc) {
        asm volatile("cp.async.wait_group 1;\n" ::: "memory");
        __syncthreads();                      // stage kc visible to all threads

        const __nv_bfloat16* base = smem + (kc % STAGES) * STG_ELEMS;
        const __nv_bfloat16* sAh = base;
        const __nv_bfloat16* sAl = base +     ARR_ELEMS;
        const __nv_bfloat16* sBh = base + 2 * ARR_ELEMS;
        const __nv_bfloat16* sBl = base + 3 * ARR_ELEMS;

        #pragma unroll
        for (int ks = 0; ks < 2; ++ks) {
            const int kb = ks * 16;
            unsigned ah[2][4], al[2][4];
            #pragma unroll
            for (int mt = 0; mt < 2; ++mt) {
                int r = wm * 32 + mt * 16 + g8;
                ah[mt][0] = *(const unsigned*)&sAh[ r      * LDS_STRIDE + kb + tq * 2];
                ah[mt][1] = *(const unsigned*)&sAh[(r + 8) * LDS_STRIDE + kb + tq * 2];
                ah[mt][2] = *(const unsigned*)&sAh[ r      * LDS_STRIDE + kb + tq * 2 + 8];
                ah[mt][3] = *(const unsigned*)&sAh[(r + 8) * LDS_STRIDE + kb + tq * 2 + 8];
                al[mt][0] = *(const unsigned*)&sAl[ r      * LDS_STRIDE + kb + tq * 2];
                al[mt][1] = *(const unsigned*)&sAl[(r + 8) * LDS_STRIDE + kb + tq * 2];
                al[mt][2] = *(const unsigned*)&sAl[ r      * LDS_STRIDE + kb + tq * 2 + 8];
                al[mt][3] = *(const unsigned*)&sAl[(r + 8) * LDS_STRIDE + kb + tq * 2 + 8];
            }
            unsigned bh[8][2], bl[8][2];
            #pragma unroll
            for (int nt = 0; nt < 8; ++nt) {
                int cn = wn * 64 + nt * 8 + g8;
                bh[nt][0] = *(const unsigned*)&sBh[cn * LDS_STRIDE + kb + tq * 2];
                bh[nt][1] = *(const unsigned*)&sBh[cn * LDS_STRIDE + kb + tq * 2 + 8];
                bl[nt][0] = *(const unsigned*)&sBl[cn * LDS_STRIDE + kb + tq * 2];
                bl[nt][1] = *(const unsigned*)&sBl[cn * LDS_STRIDE + kb + tq * 2 + 8];
            }
            #pragma unroll
            for (int mt = 0; mt < 2; ++mt)
                #pragma unroll
                for (int nt = 0; nt < 8; ++nt) {
                    mma_bf16(acc[mt][nt], ah[mt], bh[nt]);  // hi*hi
                    mma_bf16(acc[mt][nt], ah[mt], bl[nt]);  // hi*lo
                    mma_bf16(acc[mt][nt], al[mt], bh[nt]);  // lo*hi
                }
        }
        __syncthreads();                      // all reads of stage kc done
        if (kc + 2 < 8) load_stage((kc + 2) % STAGES, kc + 2);
        asm volatile("cp.async.commit_group;\n" ::: "memory");  // keep group count
    }

    // ---- epilogue: bias + exact GELU ----
    #pragma unroll
    for (int mt = 0; mt < 2; ++mt)
        #pragma unroll
        for (int nt = 0; nt < 8; ++nt) {
            int c0 = wn * 64 + nt * 8 + tq * 2;
            float b0 = bias_s[c0], b1 = bias_s[c0 + 1];
            acc[mt][nt][0] = gelu_exact(acc[mt][nt][0] + b0);
            acc[mt][nt][1] = gelu_exact(acc[mt][nt][1] + b1);
            acc[mt][nt][2] = gelu_exact(acc[mt][nt][2] + b0);
            acc[mt][nt][3] = gelu_exact(acc[mt][nt][3] + b1);
        }

    // ---- store Y (pre-split bf16 hi/lo for layers 1-3; fp32 for layer 4) ----
    if (Yh) {
        #pragma unroll
        for (int mt = 0; mt < 2; ++mt)
            #pragma unroll
            for (int nt = 0; nt < 8; ++nt) {
                int r = rb * 128 + wm * 32 + mt * 16 + g8;
                int c = cb * 128 + wn * 64 + nt * 8 + tq * 2;
                __nv_bfloat16 h0,l0,h1,l1,h2,l2,h3,l3;
                split_bf16(acc[mt][nt][0], h0, l0);
                split_bf16(acc[mt][nt][1], h1, l1);
                split_bf16(acc[mt][nt][2], h2, l2);
                split_bf16(acc[mt][nt][3], h3, l3);
                __nv_bfloat162 p;
                p.x = h0; p.y = h1; *(__nv_bfloat162*)(Yh + (size_t)r * DIMD + c)       = p;
                p.x = l0; p.y = l1; *(__nv_bfloat162*)(Yl + (size_t)r * DIMD + c)       = p;
                p.x = h2; p.y = h3; *(__nv_bfloat162*)(Yh + (size_t)(r + 8) * DIMD + c) = p;
                p.x = l2; p.y = l3; *(__nv_bfloat162*)(Yl + (size_t)(r + 8) * DIMD + c) = p;
            }
    } else {
        #pragma unroll
        for (int mt = 0; mt < 2; ++mt)
            #pragma unroll
            for (int nt = 0; nt < 8; ++nt) {
                int r = rb * 128 + wm * 32 + mt * 16 + g8;
                int c = cb * 128 + wn * 64 + nt * 8 + tq * 2;
                *(float2*)&dout[(size_t)r * DIMD + c]       = make_float2(acc[mt][nt][0], acc[mt][nt][1]);
                *(float2*)&dout[(size_t)(r + 8) * DIMD + c] = make_float2(acc[mt][nt][2], acc[mt][nt][3]);
            }
    }

    // ---- fused per-column BN stats (deterministic: no float atomics) ----
    if (do_stats) {
        #pragma unroll
        for (int nt = 0; nt < 8; ++nt) {
            float s0 = acc[0][nt][0] + acc[0][nt][2] + acc[1][nt][0] + acc[1][nt][2];
            float s1 = acc[0][nt][1] + acc[0][nt][3] + acc[1][nt][1] + acc[1][nt][3];
            float q0 = acc[0][nt][0]*acc[0][nt][0] + acc[0][nt][2]*acc[0][nt][2]
                     + acc[1][nt][0]*acc[1][nt][0] + acc[1][nt][2]*acc[1][nt][2];
            float q1 = acc[0][nt][1]*acc[0][nt][1] + acc[0][nt][3]*acc[0][nt][3]
                     + acc[1][nt][1]*acc[1][nt][1] + acc[1][nt][3]*acc[1][nt][3];
            #pragma unroll
            for (int off = 4; off < 32; off <<= 1) {   // reduce over row-groups (g8)
                s0 += __shfl_xor_sync(0xffffffffu, s0, off);
                s1 += __shfl_xor_sync(0xffffffffu, s1, off);
                q0 += __shfl_xor_sync(0xffffffffu, q0, off);
                q1 += __shfl_xor_sync(0xffffffffu, q1, off);
            }
            if (lane < 4) {
                int cl = wn * 64 + nt * 8 + lane * 2;  // lane==tq here
                csum[wm][cl] = s0; csum[wm][cl + 1] = s1;
                csq [wm][cl] = q0; csq [wm][cl + 1] = q1;
            }
        }
        __syncthreads();
        if (tid < 128) {
            float S = csum[0][tid] + csum[1][tid] + csum[2][tid] + csum[3][tid];
            float Q = csq [0][tid] + csq [1][tid] + csq [2][tid] + csq [3][tid];
            g_ps[rb * DIMD + cb * 128 + tid] = S;
            g_pq[rb * DIMD + cb * 128 + tid] = Q;
        }
    }
}

// ---------------------------------------------------------------------------
extern "C" void kernel_launch(void* const* d_in, const int* in_sizes, int n_in,
                              void* d_out, int out_size) {
    (void)in_sizes; (void)n_in; (void)out_size;
    const int*   ids   = (const int*)  d_in[0];
    const float* table = (const float*)d_in[1];
    const float* W1 = (const float*)d_in[2],  *b1 = (const float*)d_in[3];
    const float* W2 = (const float*)d_in[4],  *b2 = (const float*)d_in[5];
    const float* W3 = (const float*)d_in[6],  *b3 = (const float*)d_in[7];
    const float* W4 = (const float*)d_in[8],  *b4 = (const float*)d_in[9];
    const float* g1 = (const float*)d_in[10], *be1 = (const float*)d_in[11];
    const float* g2 = (const float*)d_in[12], *be2 = (const float*)d_in[13];
    const float* g3 = (const float*)d_in[14], *be3 = (const float*)d_in[15];
    float* out = (float*)d_out;

    cudaFuncSetAttribute(gemm_kernel, cudaFuncAttributeMaxDynamicSharedMemorySize,
                         SMEM_BYTES);

    dim3 grid(2, NRB), blk(256);

    winit_kernel<<<DIMD, DIMD>>>(W1);
    gather_kernel<<<1024, 256>>>(ids, table);   // x0 = split(table[ids])
    // layer 1: gelu(x0 @ W1 + b1) -> x1 (+stats)
    gemm_kernel<<<grid, blk, SMEM_BYTES>>>(0, 1, nullptr, 0, b1, -1, 1);
    fin_kernel<<<1, DIMD>>>(g1, be1);
    wprep_kernel<<<DIMD, DIMD>>>(W2, b2, 1, 0);
    // layer 2: gelu(bn1(x1) @ W2 + b2) -> x2 (+stats)
    gemm_kernel<<<grid, blk, SMEM_BYTES>>>(1, 2, nullptr, 1, nullptr, 0, 1);
    fin_kernel<<<1, DIMD>>>(g2, be2);
    wprep_kernel<<<DIMD, DIMD>>>(W3, b3, 2, 1);
    // layer 3: -> x1 (+stats)
    gemm_kernel<<<grid, blk, SMEM_BYTES>>>(2, 1, nullptr, 2, nullptr, 1, 1);
    fin_kernel<<<1, DIMD>>>(g3, be3);
    wprep_kernel<<<DIMD, DIMD>>>(W4, b4, 3, 2);
    // layer 4: -> d_out fp32 (no stats)
    gemm_kernel<<<grid, blk, SMEM_BYTES>>>(1, 0, out, 3, nullptr, 2, 0);
}

// round 12
// speedup vs baseline: 1.6489x; 1.2631x over previous
#include <cuda_runtime.h>
#include <cuda_bf16.h>

// ---------------------------------------------------------------------------
// StatePerturbationEncoder: gather -> [GEMM + GELU + BN]x3 -> GEMM + GELU
// BN folded into next layer's weights: (x*a + c)@W = x@(diag(a)W) + c@W
// GEMMs in split-bf16 (hi/lo) mma.sync with fp32 accumulate (~fp32 accuracy).
// R8: ldmatrix fragment loads (4x fewer shared-pipe issues), 2-stage cp.async
// pipeline at 2 CTAs/SM, parallel fin (transposed partials), shuffle wprep.
// ---------------------------------------------------------------------------

#define NROWS 32768      // B*C
#define DIMD  256
#define NRB   256        // row blocks (NROWS/128)
#define EPSF  1e-5f

#define STAGES    2
#define TILE_K    32
#define LDS_STRIDE 40                            // 32 + 8 pad; 80B rows, LDSM conflict-free
#define ARR_ELEMS (128 * LDS_STRIDE)             // 5120 bf16 per array
#define ARR_BYTES (ARR_ELEMS * 2)                // 10240
#define STG_BYTES (4 * ARR_BYTES)                // 40960 (Ah|Al|Bh|Bl)
#define SMEM_BYTES (STAGES * STG_BYTES)          // 81920 -> 2 CTAs/SM

// ----- scratch (static device globals; allocation-free at runtime) ---------
__device__ __align__(256) static __nv_bfloat16 g_x0h[NROWS*DIMD], g_x0l[NROWS*DIMD];
__device__ __align__(256) static __nv_bfloat16 g_x1h[NROWS*DIMD], g_x1l[NROWS*DIMD];
__device__ __align__(256) static __nv_bfloat16 g_x2h[NROWS*DIMD], g_x2l[NROWS*DIMD];
__device__ __align__(256) static float g_ps[DIMD * NRB];   // TRANSPOSED: [col][rb]
__device__ __align__(256) static float g_pq[DIMD * NRB];
__device__ __align__(256) static __nv_bfloat16 g_w1h[DIMD*DIMD], g_w1l[DIMD*DIMD];
__device__ __align__(256) static __nv_bfloat16 g_w2h[DIMD*DIMD], g_w2l[DIMD*DIMD];
__device__ __align__(256) static __nv_bfloat16 g_w3h[DIMD*DIMD], g_w3l[DIMD*DIMD];
__device__ __align__(256) static __nv_bfloat16 g_w4h[DIMD*DIMD], g_w4l[DIMD*DIMD];
__device__ __align__(256) static float g_a[DIMD], g_c[DIMD];
__device__ __align__(256) static float g_bp[3][DIMD];      // folded biases, layers 2..4

// ----- helpers -------------------------------------------------------------
__device__ __forceinline__ void split_bf16(float x, __nv_bfloat16& h, __nv_bfloat16& l) {
    h = __float2bfloat16(x);
    l = __float2bfloat16(x - __bfloat162float(h));
}

__device__ __forceinline__ float gelu_exact(float x) {
    return x * normcdff(x);   // x * Phi(x), matches jax.nn.gelu(approximate=False)
}

__device__ __forceinline__ void mma_bf16(float* d, const unsigned* a, const unsigned* b) {
    asm volatile(
        "mma.sync.aligned.m16n8k16.row.col.f32.bf16.bf16.f32 "
        "{%0,%1,%2,%3}, {%4,%5,%6,%7}, {%8,%9}, {%0,%1,%2,%3};\n"
        : "+f"(d[0]), "+f"(d[1]), "+f"(d[2]), "+f"(d[3])
        : "r"(a[0]), "r"(a[1]), "r"(a[2]), "r"(a[3]), "r"(b[0]), "r"(b[1]));
}

__device__ __forceinline__ void ldsm4(unsigned& r0, unsigned& r1, unsigned& r2, unsigned& r3,
                                      unsigned addr) {
    asm volatile("ldmatrix.sync.aligned.m8n8.x4.shared.b16 {%0,%1,%2,%3}, [%4];\n"
        : "=r"(r0), "=r"(r1), "=r"(r2), "=r"(r3) : "r"(addr));
}

__device__ __forceinline__ void cp_async16(unsigned sdst, const __nv_bfloat16* gsrc) {
    asm volatile("cp.async.cg.shared.global [%0], [%1], 16;\n" :: "r"(sdst), "l"(gsrc) : "memory");
}

// ----- gather + split: x0 = split(table[ids]) -------------------------------
__global__ void gather_kernel(const int* __restrict__ ids, const float* __restrict__ table) {
    int t = blockIdx.x * blockDim.x + threadIdx.x;     // 262144 threads
    #pragma unroll
    for (int i = 0; i < 8; ++i) {
        int c   = t + (i << 18);                       // float4 chunk id
        int row = c >> 6;                              // 64 float4 per row
        int seg = (c & 63) << 2;                       // float offset in row
        const float* src = table + (size_t)ids[row] * DIMD + seg;
        float4 v = *(const float4*)src;
        __nv_bfloat16 h0,l0,h1,l1,h2,l2,h3,l3;
        split_bf16(v.x, h0, l0); split_bf16(v.y, h1, l1);
        split_bf16(v.z, h2, l2); split_bf16(v.w, h3, l3);
        size_t off = (size_t)row * DIMD + seg;
        __nv_bfloat162 p;
        p.x = h0; p.y = h1; *(__nv_bfloat162*)(g_x0h + off)     = p;
        p.x = h2; p.y = h3; *(__nv_bfloat162*)(g_x0h + off + 2) = p;
        p.x = l0; p.y = l1; *(__nv_bfloat162*)(g_x0l + off)     = p;
        p.x = l2; p.y = l3; *(__nv_bfloat162*)(g_x0l + off + 2) = p;
    }
}

// ----- W1 transpose + split (layer-1 weights, no BN folding) ---------------
__global__ void winit_kernel(const float* __restrict__ W1) {
    int j = blockIdx.x, k = threadIdx.x;       // j = out col, k = in dim
    __nv_bfloat16 h, l;
    split_bf16(W1[k * DIMD + j], h, l);
    g_w1h[j * DIMD + k] = h;                   // stored [n][k] (transposed)
    g_w1l[j * DIMD + k] = l;
}

// ----- finalize BN stats (parallel): one block per column ------------------
__global__ void fin_kernel(const float* __restrict__ gam, const float* __restrict__ bet) {
    int j = blockIdx.x, t = threadIdx.x;
    int warp = t >> 5, lane = t & 31;
    float s = g_ps[j * NRB + t];               // coalesced
    float q = g_pq[j * NRB + t];
    #pragma unroll
    for (int off = 16; off > 0; off >>= 1) {   // fixed order -> deterministic
        s += __shfl_xor_sync(0xffffffffu, s, off);
        q += __shfl_xor_sync(0xffffffffu, q, off);
    }
    __shared__ float ss[8], qq[8];
    if (lane == 0) { ss[warp] = s; qq[warp] = q; }
    __syncthreads();
    if (t == 0) {
        float S = ss[0] + ss[1] + ss[2] + ss[3] + ss[4] + ss[5] + ss[6] + ss[7];
        float Q = qq[0] + qq[1] + qq[2] + qq[3] + qq[4] + qq[5] + qq[6] + qq[7];
        const float invn = 1.0f / (float)NROWS;
        float mu  = S * invn;
        float var = Q * invn - mu * mu;
        if (var < 0.f) var = 0.f;
        float ai  = gam[j] * rsqrtf(var + EPSF);
        g_a[j] = ai;
        g_c[j] = bet[j] - mu * ai;
    }
}

// ----- fold BN into next layer: W' = diag(a)W (transposed hi/lo), b' = b + c@W
__global__ void wprep_kernel(const float* __restrict__ W, const float* __restrict__ b,
                             int wsel, int bidx) {
    int j = blockIdx.x, k = threadIdx.x;
    int warp = k >> 5, lane = k & 31;
    float w  = W[k * DIMD + j];
    float wp = g_a[k] * w;
    __nv_bfloat16 h, l;
    split_bf16(wp, h, l);
    __nv_bfloat16 *Wh, *Wl;
    switch (wsel) {
        case 1:  Wh = g_w2h; Wl = g_w2l; break;
        case 2:  Wh = g_w3h; Wl = g_w3l; break;
        default: Wh = g_w4h; Wl = g_w4l; break;
    }
    Wh[j * DIMD + k] = h;
    Wl[j * DIMD + k] = l;

    float v = g_c[k] * w;
    #pragma unroll
    for (int off = 16; off > 0; off >>= 1)
        v += __shfl_xor_sync(0xffffffffu, v, off);
    __shared__ float r8[8];
    if (lane == 0) r8[warp] = v;
    __syncthreads();
    if (k == 0) {
        float R = r8[0] + r8[1] + r8[2] + r8[3] + r8[4] + r8[5] + r8[6] + r8[7];
        g_bp[bidx][j] = b[j] + R;
    }
}

// ----- fused GEMM: Y = gelu(X @ W'^T(hi/lo) + bias), + per-column stats ----
// block tile 128x128, K-chunks of 32, 8 warps (4M x 2N), warp tile 32x64
// 2-stage cp.async pipeline, ldmatrix fragment loads, 2 CTAs/SM.
__global__ __launch_bounds__(256, 2)
void gemm_kernel(int xsel, int ysel, float* __restrict__ dout,
                 int wsel, const float* __restrict__ bias_ext, int bidx,
                 int do_stats) {
    const __nv_bfloat16 *Xh, *Xl;
    if      (xsel == 0) { Xh = g_x0h; Xl = g_x0l; }
    else if (xsel == 1) { Xh = g_x1h; Xl = g_x1l; }
    else                { Xh = g_x2h; Xl = g_x2l; }
    __nv_bfloat16 *Yh = nullptr, *Yl = nullptr;
    if      (ysel == 1) { Yh = g_x1h; Yl = g_x1l; }
    else if (ysel == 2) { Yh = g_x2h; Yl = g_x2l; }
    const __nv_bfloat16 *Wh, *Wl;
    switch (wsel) {
        case 0:  Wh = g_w1h; Wl = g_w1l; break;
        case 1:  Wh = g_w2h; Wl = g_w2l; break;
        case 2:  Wh = g_w3h; Wl = g_w3l; break;
        default: Wh = g_w4h; Wl = g_w4l; break;
    }
    const float* bias = (bidx >= 0) ? g_bp[bidx] : bias_ext;

    extern __shared__ __align__(16) __nv_bfloat16 smem[];   // [2][Ah|Al|Bh|Bl][128][40]
    __shared__ float bias_s[128];
    __shared__ float csum[4][128], csq[4][128];

    const int tid  = threadIdx.x;
    const int rb   = blockIdx.y, cb = blockIdx.x;
    const int warp = tid >> 5, lane = tid & 31;
    const int wm   = warp & 3,  wn  = warp >> 2;
    const int g8   = lane >> 2, tq  = lane & 3;

    if (tid < 128) bias_s[tid] = bias[cb * 128 + tid];

    const __nv_bfloat16* Xhb = Xh + (size_t)(rb * 128) * DIMD;
    const __nv_bfloat16* Xlb = Xl + (size_t)(rb * 128) * DIMD;
    const __nv_bfloat16* Whb = Wh + (size_t)(cb * 128) * DIMD;
    const __nv_bfloat16* Wlb = Wl + (size_t)(cb * 128) * DIMD;

    const unsigned smem_u32 = (unsigned)__cvta_generic_to_shared(smem);

    // cp.async geometry: thread covers rows r0, r0+64 of each array, 16B seg s8
    const int r0 = tid >> 2;
    const int s8 = (tid & 3) * 8;            // bf16 element offset within row

    auto load_stage = [&](int st, int kc) {
        unsigned base = smem_u32 + st * STG_BYTES;
        const int koff = kc * TILE_K + s8;
        const int r1 = r0 + 64;
        unsigned d0 = base + (r0 * LDS_STRIDE + s8) * 2;
        unsigned d1 = base + (r1 * LDS_STRIDE + s8) * 2;
        cp_async16(d0,                 Xhb + (size_t)r0 * DIMD + koff);
        cp_async16(d0 +     ARR_BYTES, Xlb + (size_t)r0 * DIMD + koff);
        cp_async16(d0 + 2 * ARR_BYTES, Whb + (size_t)r0 * DIMD + koff);
        cp_async16(d0 + 3 * ARR_BYTES, Wlb + (size_t)r0 * DIMD + koff);
        cp_async16(d1,                 Xhb + (size_t)r1 * DIMD + koff);
        cp_async16(d1 +     ARR_BYTES, Xlb + (size_t)r1 * DIMD + koff);
        cp_async16(d1 + 2 * ARR_BYTES, Whb + (size_t)r1 * DIMD + koff);
        cp_async16(d1 + 3 * ARR_BYTES, Wlb + (size_t)r1 * DIMD + koff);
    };

    // ldmatrix per-lane byte offsets (within one array of a stage)
    const int lr = lane & 7, m8 = lane >> 3;
    const int arow = (m8 & 1) * 8 + lr;        // mats: (r,kb)(r+8,kb)(r,kb+8)(r+8,kb+8)
    const int acolB = (m8 >> 1) * 16;
    const int brow = (m8 >> 1) * 8 + lr;       // mats: (nt0,kb)(nt0,kb+8)(nt1,kb)(nt1,kb+8)
    const int bcolB = (m8 & 1) * 16;
    const unsigned aoff0 = (unsigned)((wm * 32 + arow) * LDS_STRIDE * 2 + acolB);
    const unsigned aoff1 = aoff0 + 16 * LDS_STRIDE * 2;
    unsigned boff[4];
    #pragma unroll
    for (int p = 0; p < 4; ++p)
        boff[p] = (unsigned)(((wn * 64 + p * 16 + brow) * LDS_STRIDE) * 2 + bcolB);

    float acc[2][8][4];
    #pragma unroll
    for (int mt = 0; mt < 2; ++mt)
        #pragma unroll
        for (int nt = 0; nt < 8; ++nt)
            #pragma unroll
            for (int e = 0; e < 4; ++e) acc[mt][nt][e] = 0.f;

    load_stage(0, 0);
    asm volatile("cp.async.commit_group;\n" ::: "memory");

    for (int kc = 0; kc < 8; ++kc) {
        if (kc < 7) {
            load_stage((kc + 1) & 1, kc + 1);
            asm volatile("cp.async.commit_group;\n" ::: "memory");
            asm volatile("cp.async.wait_group 1;\n" ::: "memory");
        } else {
            asm volatile("cp.async.wait_group 0;\n" ::: "memory");
        }
        __syncthreads();                      // stage kc visible

        unsigned sbase = smem_u32 + (kc & 1) * STG_BYTES;
        #pragma unroll
        for (int ks = 0; ks < 2; ++ks) {
            const unsigned kbB = ks * 32;     // 16 bf16 = 32 bytes
            unsigned ah[8], al[8];
            ldsm4(ah[0], ah[1], ah[2], ah[3], sbase + aoff0 + kbB);
            ldsm4(ah[4], ah[5], ah[6], ah[7], sbase + aoff1 + kbB);
            ldsm4(al[0], al[1], al[2], al[3], sbase + ARR_BYTES + aoff0 + kbB);
            ldsm4(al[4], al[5], al[6], al[7], sbase + ARR_BYTES + aoff1 + kbB);
            #pragma unroll
            for (int p = 0; p < 4; ++p) {
                unsigned bh4[4], bl4[4];
                ldsm4(bh4[0], bh4[1], bh4[2], bh4[3], sbase + 2 * ARR_BYTES + boff[p] + kbB);
                ldsm4(bl4[0], bl4[1], bl4[2], bl4[3], sbase + 3 * ARR_BYTES + boff[p] + kbB);
                #pragma unroll
                for (int q = 0; q < 2; ++q) {
                    const int nt = p * 2 + q;
                    #pragma unroll
                    for (int mt = 0; mt < 2; ++mt) {
                        mma_bf16(acc[mt][nt], &ah[mt * 4], &bh4[q * 2]);  // hi*hi
                        mma_bf16(acc[mt][nt], &ah[mt * 4], &bl4[q * 2]);  // hi*lo
                        mma_bf16(acc[mt][nt], &al[mt * 4], &bh4[q * 2]);  // lo*hi
                    }
                }
            }
        }
        __syncthreads();                      // reads done before next overwrite
    }

    // ---- epilogue: bias + exact GELU ----
    #pragma unroll
    for (int mt = 0; mt < 2; ++mt)
        #pragma unroll
        for (int nt = 0; nt < 8; ++nt) {
            int c0 = wn * 64 + nt * 8 + tq * 2;
            float b0 = bias_s[c0], b1 = bias_s[c0 + 1];
            acc[mt][nt][0] = gelu_exact(acc[mt][nt][0] + b0);
            acc[mt][nt][1] = gelu_exact(acc[mt][nt][1] + b1);
            acc[mt][nt][2] = gelu_exact(acc[mt][nt][2] + b0);
            acc[mt][nt][3] = gelu_exact(acc[mt][nt][3] + b1);
        }

    // ---- store Y (pre-split bf16 hi/lo for layers 1-3; fp32 for layer 4) ----
    if (Yh) {
        #pragma unroll
        for (int mt = 0; mt < 2; ++mt)
            #pragma unroll
            for (int nt = 0; nt < 8; ++nt) {
                int r = rb * 128 + wm * 32 + mt * 16 + g8;
                int c = cb * 128 + wn * 64 + nt * 8 + tq * 2;
                __nv_bfloat16 h0,l0,h1,l1,h2,l2,h3,l3;
                split_bf16(acc[mt][nt][0], h0, l0);
                split_bf16(acc[mt][nt][1], h1, l1);
                split_bf16(acc[mt][nt][2], h2, l2);
                split_bf16(acc[mt][nt][3], h3, l3);
                __nv_bfloat162 p;
                p.x = h0; p.y = h1; *(__nv_bfloat162*)(Yh + (size_t)r * DIMD + c)       = p;
                p.x = l0; p.y = l1; *(__nv_bfloat162*)(Yl + (size_t)r * DIMD + c)       = p;
                p.x = h2; p.y = h3; *(__nv_bfloat162*)(Yh + (size_t)(r + 8) * DIMD + c) = p;
                p.x = l2; p.y = l3; *(__nv_bfloat162*)(Yl + (size_t)(r + 8) * DIMD + c) = p;
            }
    } else {
        #pragma unroll
        for (int mt = 0; mt < 2; ++mt)
            #pragma unroll
            for (int nt = 0; nt < 8; ++nt) {
                int r = rb * 128 + wm * 32 + mt * 16 + g8;
                int c = cb * 128 + wn * 64 + nt * 8 + tq * 2;
                *(float2*)&dout[(size_t)r * DIMD + c]       = make_float2(acc[mt][nt][0], acc[mt][nt][1]);
                *(float2*)&dout[(size_t)(r + 8) * DIMD + c] = make_float2(acc[mt][nt][2], acc[mt][nt][3]);
            }
    }

    // ---- fused per-column BN stats (deterministic; transposed partials) ----
    if (do_stats) {
        #pragma unroll
        for (int nt = 0; nt < 8; ++nt) {
            float s0 = acc[0][nt][0] + acc[0][nt][2] + acc[1][nt][0] + acc[1][nt][2];
            float s1 = acc[0][nt][1] + acc[0][nt][3] + acc[1][nt][1] + acc[1][nt][3];
            float q0 = acc[0][nt][0]*acc[0][nt][0] + acc[0][nt][2]*acc[0][nt][2]
                     + acc[1][nt][0]*acc[1][nt][0] + acc[1][nt][2]*acc[1][nt][2];
            float q1 = acc[0][nt][1]*acc[0][nt][1] + acc[0][nt][3]*acc[0][nt][3]
                     + acc[1][nt][1]*acc[1][nt][1] + acc[1][nt][3]*acc[1][nt][3];
            #pragma unroll
            for (int off = 4; off < 32; off <<= 1) {   // reduce over row-groups (g8)
                s0 += __shfl_xor_sync(0xffffffffu, s0, off);
                s1 += __shfl_xor_sync(0xffffffffu, s1, off);
                q0 += __shfl_xor_sync(0xffffffffu, q0, off);
                q1 += __shfl_xor_sync(0xffffffffu, q1, off);
            }
            if (lane < 4) {
                int cl = wn * 64 + nt * 8 + lane * 2;  // lane==tq here
                csum[wm][cl] = s0; csum[wm][cl + 1] = s1;
                csq [wm][cl] = q0; csq [wm][cl + 1] = q1;
            }
        }
        __syncthreads();
        if (tid < 128) {
            float S = csum[0][tid] + csum[1][tid] + csum[2][tid] + csum[3][tid];
            float Q = csq [0][tid] + csq [1][tid] + csq [2][tid] + csq [3][tid];
            g_ps[(cb * 128 + tid) * NRB + rb] = S;     // transposed for parallel fin
            g_pq[(cb * 128 + tid) * NRB + rb] = Q;
        }
    }
}

// ---------------------------------------------------------------------------
extern "C" void kernel_launch(void* const* d_in, const int* in_sizes, int n_in,
                              void* d_out, int out_size) {
    (void)in_sizes; (void)n_in; (void)out_size;
    const int*   ids   = (const int*)  d_in[0];
    const float* table = (const float*)d_in[1];
    const float* W1 = (const float*)d_in[2],  *b1 = (const float*)d_in[3];
    const float* W2 = (const float*)d_in[4],  *b2 = (const float*)d_in[5];
    const float* W3 = (const float*)d_in[6],  *b3 = (const float*)d_in[7];
    const float* W4 = (const float*)d_in[8],  *b4 = (const float*)d_in[9];
    const float* g1 = (const float*)d_in[10], *be1 = (const float*)d_in[11];
    const float* g2 = (const float*)d_in[12], *be2 = (const float*)d_in[13];
    const float* g3 = (const float*)d_in[14], *be3 = (const float*)d_in[15];
    float* out = (float*)d_out;

    cudaFuncSetAttribute(gemm_kernel, cudaFuncAttributeMaxDynamicSharedMemorySize,
                         SMEM_BYTES);

    dim3 grid(2, NRB), blk(256);

    winit_kernel<<<DIMD, DIMD>>>(W1);
    gather_kernel<<<1024, 256>>>(ids, table);   // x0 = split(table[ids])
    // layer 1: gelu(x0 @ W1 + b1) -> x1 (+stats)
    gemm_kernel<<<grid, blk, SMEM_BYTES>>>(0, 1, nullptr, 0, b1, -1, 1);
    fin_kernel<<<DIMD, 256>>>(g1, be1);
    wprep_kernel<<<DIMD, DIMD>>>(W2, b2, 1, 0);
    // layer 2: gelu(bn1(x1) @ W2 + b2) -> x2 (+stats)
    gemm_kernel<<<grid, blk, SMEM_BYTES>>>(1, 2, nullptr, 1, nullptr, 0, 1);
    fin_kernel<<<DIMD, 256>>>(g2, be2);
    wprep_kernel<<<DIMD, DIMD>>>(W3, b3, 2, 1);
    // layer 3: -> x1 (+stats)
    gemm_kernel<<<grid, blk, SMEM_BYTES>>>(2, 1, nullptr, 2, nullptr, 1, 1);
    fin_kernel<<<DIMD, 256>>>(g3, be3);
    wprep_kernel<<<DIMD, DIMD>>>(W4, b4, 3, 2);
    // layer 4: -> d_out fp32 (no stats)
    gemm_kernel<<<grid, blk, SMEM_BYTES>>>(1, 0, out, 3, nullptr, 2, 0);
}

// round 15
// speedup vs baseline: 1.9955x; 1.2102x over previous
#include <cuda_runtime.h>
#include <cuda_bf16.h>
#include <cstdint>

// ---------------------------------------------------------------------------
// StatePerturbationEncoder: gather -> [GEMM + GELU + BN]x3 -> GEMM + GELU
// R15: DEDUP BY PERT ID. Every layer's output depends only on the pert id, so
// the whole MLP runs over 20096 (padded) unique rows instead of 32768; the
// batch result is one fp32 gather at the end. BN batch stats over the real
// 32768-row batch are recovered exactly as count-weighted sums (integer
// histogram -> deterministic). BN folded into next layer's weights.
// GEMMs: split-bf16 (hi/lo) mma.sync, 2-stage cp.async, ldmatrix, 2 CTA/SM.
// ---------------------------------------------------------------------------

#define NROWS 32768      // B*C (real batch)
#define NPERT 20000
#define NU    20096      // padded unique rows (157 * 128)
#define NRBU  157        // row blocks over unique rows
#define DIMD  256
#define EPSF  1e-5f

#define TILE_K    32
#define LDS_STRIDE 40                            // 32 + 8 pad; LDSM conflict-free
#define ARR_ELEMS (128 * LDS_STRIDE)             // 5120 bf16 per array
#define ARR_BYTES (ARR_ELEMS * 2)                // 10240
#define STG_BYTES (4 * ARR_BYTES)                // 40960 (Ah|Al|Bh|Bl)
#define SMEM_BYTES (2 * STG_BYTES)               // 81920 -> 2 CTAs/SM

// ----- scratch (static device globals; allocation-free at runtime) ---------
__device__ __align__(256) static __nv_bfloat16 g_x0h[NU*DIMD], g_x0l[NU*DIMD];
__device__ __align__(256) static __nv_bfloat16 g_x1h[NU*DIMD], g_x1l[NU*DIMD];
__device__ __align__(256) static __nv_bfloat16 g_x2h[NU*DIMD], g_x2l[NU*DIMD];
__device__ __align__(256) static float g_y4[NU*DIMD];      // final fp32 (pre-gather)
__device__ __align__(256) static int   g_cnt[NU];          // pert occurrence counts
__device__ __align__(256) static float g_ps[DIMD * NRBU];  // TRANSPOSED: [col][rb]
__device__ __align__(256) static float g_pq[DIMD * NRBU];
__device__ __align__(256) static __nv_bfloat16 g_w1h[DIMD*DIMD], g_w1l[DIMD*DIMD];
__device__ __align__(256) static __nv_bfloat16 g_w2h[DIMD*DIMD], g_w2l[DIMD*DIMD];
__device__ __align__(256) static __nv_bfloat16 g_w3h[DIMD*DIMD], g_w3l[DIMD*DIMD];
__device__ __align__(256) static __nv_bfloat16 g_w4h[DIMD*DIMD], g_w4l[DIMD*DIMD];
__device__ __align__(256) static float g_a[DIMD], g_c[DIMD];
__device__ __align__(256) static float g_bp[3][DIMD];      // folded biases, layers 2..4

// ----- helpers -------------------------------------------------------------
__device__ __forceinline__ void split_bf16(float x, __nv_bfloat16& h, __nv_bfloat16& l) {
    h = __float2bfloat16(x);
    l = __float2bfloat16(x - __bfloat162float(h));
}

__device__ __forceinline__ float gelu_exact(float x) {
    return x * normcdff(x);   // x * Phi(x), matches jax.nn.gelu(approximate=False)
}

__device__ __forceinline__ void mma_bf16(float* d, const unsigned* a, const unsigned* b) {
    asm volatile(
        "mma.sync.aligned.m16n8k16.row.col.f32.bf16.bf16.f32 "
        "{%0,%1,%2,%3}, {%4,%5,%6,%7}, {%8,%9}, {%0,%1,%2,%3};\n"
        : "+f"(d[0]), "+f"(d[1]), "+f"(d[2]), "+f"(d[3])
        : "r"(a[0]), "r"(a[1]), "r"(a[2]), "r"(a[3]), "r"(b[0]), "r"(b[1]));
}

__device__ __forceinline__ void ldsm4(unsigned& r0, unsigned& r1, unsigned& r2, unsigned& r3,
                                      unsigned addr) {
    asm volatile("ldmatrix.sync.aligned.m8n8.x4.shared.b16 {%0,%1,%2,%3}, [%4];\n"
        : "=r"(r0), "=r"(r1), "=r"(r2), "=r"(r3) : "r"(addr));
}

__device__ __forceinline__ void cp_async16(unsigned sdst, const __nv_bfloat16* gsrc) {
    asm volatile("cp.async.cg.shared.global [%0], [%1], 16;\n" :: "r"(sdst), "l"(gsrc) : "memory");
}

// ----- split table rows into x0 (unique-pert inputs; pad rows = 0) ----------
__global__ void split_table_kernel(const float* __restrict__ table) {
    int idx = blockIdx.x * blockDim.x + threadIdx.x;   // one float4 per thread
    int row = idx >> 6;                                // 64 float4 per row
    int seg = (idx & 63) << 2;
    float4 v = make_float4(0.f, 0.f, 0.f, 0.f);
    if (row < NPERT) v = *(const float4*)(table + (size_t)row * DIMD + seg);
    __nv_bfloat16 h0,l0,h1,l1,h2,l2,h3,l3;
    split_bf16(v.x, h0, l0); split_bf16(v.y, h1, l1);
    split_bf16(v.z, h2, l2); split_bf16(v.w, h3, l3);
    size_t off = (size_t)row * DIMD + seg;
    __nv_bfloat162 p;
    p.x = h0; p.y = h1; *(__nv_bfloat162*)(g_x0h + off)     = p;
    p.x = h2; p.y = h3; *(__nv_bfloat162*)(g_x0h + off + 2) = p;
    p.x = l0; p.y = l1; *(__nv_bfloat162*)(g_x0l + off)     = p;
    p.x = l2; p.y = l3; *(__nv_bfloat162*)(g_x0l + off + 2) = p;
}

// ----- histogram of pert ids (int atomics -> deterministic) ----------------
__global__ void zero_cnt_kernel() {
    int t = blockIdx.x * blockDim.x + threadIdx.x;
    if (t < NU) g_cnt[t] = 0;
}
__global__ void hist_kernel(const int* __restrict__ ids) {
    int t = blockIdx.x * blockDim.x + threadIdx.x;     // 32768 threads
    atomicAdd(&g_cnt[ids[t]], 1);
}

// ----- W1 transpose + split (layer-1 weights, no BN folding) ---------------
__global__ void winit_kernel(const float* __restrict__ W1) {
    int j = blockIdx.x, k = threadIdx.x;       // j = out col, k = in dim
    __nv_bfloat16 h, l;
    split_bf16(W1[k * DIMD + j], h, l);
    g_w1h[j * DIMD + k] = h;                   // stored [n][k] (transposed)
    g_w1l[j * DIMD + k] = l;
}

// ----- finalize BN stats (parallel): one block per column ------------------
__global__ void fin_kernel(const float* __restrict__ gam, const float* __restrict__ bet) {
    int j = blockIdx.x, t = threadIdx.x;
    int warp = t >> 5, lane = t & 31;
    float s = 0.f, q = 0.f;
    if (t < NRBU) {                            // 157 partial blocks
        s = g_ps[j * NRBU + t];
        q = g_pq[j * NRBU + t];
    }
    #pragma unroll
    for (int off = 16; off > 0; off >>= 1) {   // fixed order -> deterministic
        s += __shfl_xor_sync(0xffffffffu, s, off);
        q += __shfl_xor_sync(0xffffffffu, q, off);
    }
    __shared__ float ss[8], qq[8];
    if (lane == 0) { ss[warp] = s; qq[warp] = q; }
    __syncthreads();
    if (t == 0) {
        float S = ss[0] + ss[1] + ss[2] + ss[3] + ss[4] + ss[5] + ss[6] + ss[7];
        float Q = qq[0] + qq[1] + qq[2] + qq[3] + qq[4] + qq[5] + qq[6] + qq[7];
        const float invn = 1.0f / (float)NROWS;   // weighted stats over REAL batch
        float mu  = S * invn;
        float var = Q * invn - mu * mu;
        if (var < 0.f) var = 0.f;
        float ai  = gam[j] * rsqrtf(var + EPSF);
        g_a[j] = ai;
        g_c[j] = bet[j] - mu * ai;
    }
}

// ----- fold BN into next layer: W' = diag(a)W (transposed hi/lo), b' = b + c@W
__global__ void wprep_kernel(const float* __restrict__ W, const float* __restrict__ b,
                             int wsel, int bidx) {
    int j = blockIdx.x, k = threadIdx.x;
    int warp = k >> 5, lane = k & 31;
    float w  = W[k * DIMD + j];
    float wp = g_a[k] * w;
    __nv_bfloat16 h, l;
    split_bf16(wp, h, l);
    __nv_bfloat16 *Wh, *Wl;
    switch (wsel) {
        case 1:  Wh = g_w2h; Wl = g_w2l; break;
        case 2:  Wh = g_w3h; Wl = g_w3l; break;
        default: Wh = g_w4h; Wl = g_w4l; break;
    }
    Wh[j * DIMD + k] = h;
    Wl[j * DIMD + k] = l;

    float v = g_c[k] * w;
    #pragma unroll
    for (int off = 16; off > 0; off >>= 1)
        v += __shfl_xor_sync(0xffffffffu, v, off);
    __shared__ float r8[8];
    if (lane == 0) r8[warp] = v;
    __syncthreads();
    if (k == 0) {
        float R = r8[0] + r8[1] + r8[2] + r8[3] + r8[4] + r8[5] + r8[6] + r8[7];
        g_bp[bidx][j] = b[j] + R;
    }
}

// ----- final gather: out[b,c] = y4[ids[b,c]] (fp32) -------------------------
__global__ void gather_out_kernel(const int* __restrict__ ids, float* __restrict__ out) {
    int t = blockIdx.x * blockDim.x + threadIdx.x;     // 524288 threads
    #pragma unroll
    for (int i = 0; i < 4; ++i) {
        int c   = t + (i << 19);                       // float4 chunk id
        int row = c >> 6;
        int seg = (c & 63) << 2;
        float4 v = *(const float4*)(g_y4 + (size_t)ids[row] * DIMD + seg);
        *(float4*)(out + (size_t)row * DIMD + seg) = v;
    }
}

// ----- fused GEMM over unique rows: Y = gelu(X @ W'^T(hi/lo) + bias) -------
// block tile 128x128, K-chunks of 32, 8 warps (4M x 2N), warp tile 32x64
// 2-stage cp.async pipeline, ldmatrix, 2 CTAs/SM; count-weighted BN stats.
__global__ __launch_bounds__(256, 2)
void gemm_kernel(int xsel, int ysel,
                 int wsel, const float* __restrict__ bias_ext, int bidx,
                 int do_stats) {
    const __nv_bfloat16 *Xh, *Xl;
    if      (xsel == 0) { Xh = g_x0h; Xl = g_x0l; }
    else if (xsel == 1) { Xh = g_x1h; Xl = g_x1l; }
    else                { Xh = g_x2h; Xl = g_x2l; }
    __nv_bfloat16 *Yh = nullptr, *Yl = nullptr;
    if      (ysel == 1) { Yh = g_x1h; Yl = g_x1l; }
    else if (ysel == 2) { Yh = g_x2h; Yl = g_x2l; }
    const __nv_bfloat16 *Wh, *Wl;
    switch (wsel) {
        case 0:  Wh = g_w1h; Wl = g_w1l; break;
        case 1:  Wh = g_w2h; Wl = g_w2l; break;
        case 2:  Wh = g_w3h; Wl = g_w3l; break;
        default: Wh = g_w4h; Wl = g_w4l; break;
    }
    const float* bias = (bidx >= 0) ? g_bp[bidx] : bias_ext;

    extern __shared__ __align__(16) __nv_bfloat16 smem[];   // [2][Ah|Al|Bh|Bl][128][40]
    __shared__ float bias_s[128];
    __shared__ float cw_s[128];
    __shared__ float csum[4][128], csq[4][128];

    const int tid  = threadIdx.x;
    const int rb   = blockIdx.y, cb = blockIdx.x;
    const int warp = tid >> 5, lane = tid & 31;
    const int wm   = warp & 3,  wn  = warp >> 2;
    const int g8   = lane >> 2, tq  = lane & 3;

    if (tid < 128) {
        bias_s[tid] = bias[cb * 128 + tid];
        cw_s[tid]   = (float)g_cnt[rb * 128 + tid];   // stats weights
    }

    const __nv_bfloat16* Xhb = Xh + (size_t)(rb * 128) * DIMD;
    const __nv_bfloat16* Xlb = Xl + (size_t)(rb * 128) * DIMD;
    const __nv_bfloat16* Whb = Wh + (size_t)(cb * 128) * DIMD;
    const __nv_bfloat16* Wlb = Wl + (size_t)(cb * 128) * DIMD;

    const unsigned smem_u32 = (unsigned)__cvta_generic_to_shared(smem);

    // cp.async geometry: thread covers rows r0, r0+64 of each array, 16B seg s8
    const int r0 = tid >> 2;
    const int s8 = (tid & 3) * 8;            // bf16 element offset within row

    auto load_stage = [&](int st, int kc) {
        unsigned base = smem_u32 + st * STG_BYTES;
        const int koff = kc * TILE_K + s8;
        const int r1 = r0 + 64;
        unsigned d0 = base + (r0 * LDS_STRIDE + s8) * 2;
        unsigned d1 = base + (r1 * LDS_STRIDE + s8) * 2;
        cp_async16(d0,                 Xhb + (size_t)r0 * DIMD + koff);
        cp_async16(d0 +     ARR_BYTES, Xlb + (size_t)r0 * DIMD + koff);
        cp_async16(d0 + 2 * ARR_BYTES, Whb + (size_t)r0 * DIMD + koff);
        cp_async16(d0 + 3 * ARR_BYTES, Wlb + (size_t)r0 * DIMD + koff);
        cp_async16(d1,                 Xhb + (size_t)r1 * DIMD + koff);
        cp_async16(d1 +     ARR_BYTES, Xlb + (size_t)r1 * DIMD + koff);
        cp_async16(d1 + 2 * ARR_BYTES, Whb + (size_t)r1 * DIMD + koff);
        cp_async16(d1 + 3 * ARR_BYTES, Wlb + (size_t)r1 * DIMD + koff);
    };

    // ldmatrix per-lane byte offsets (within one array of a stage)
    const int lr = lane & 7, m8 = lane >> 3;
    const int arow = (m8 & 1) * 8 + lr;        // mats: (r,kb)(r+8,kb)(r,kb+8)(r+8,kb+8)
    const int acolB = (m8 >> 1) * 16;
    const int brow = (m8 >> 1) * 8 + lr;       // mats: (nt0,kb)(nt0,kb+8)(nt1,kb)(nt1,kb+8)
    const int bcolB = (m8 & 1) * 16;
    const unsigned aoff0 = (unsigned)((wm * 32 + arow) * LDS_STRIDE * 2 + acolB);
    const unsigned aoff1 = aoff0 + 16 * LDS_STRIDE * 2;
    unsigned boff[4];
    #pragma unroll
    for (int p = 0; p < 4; ++p)
        boff[p] = (unsigned)(((wn * 64 + p * 16 + brow) * LDS_STRIDE) * 2 + bcolB);

    float acc[2][8][4];
    #pragma unroll
    for (int mt = 0; mt < 2; ++mt)
        #pragma unroll
        for (int nt = 0; nt < 8; ++nt)
            #pragma unroll
            for (int e = 0; e < 4; ++e) acc[mt][nt][e] = 0.f;

    load_stage(0, 0);
    asm volatile("cp.async.commit_group;\n" ::: "memory");

    for (int kc = 0; kc < 8; ++kc) {
        if (kc < 7) {
            load_stage((kc + 1) & 1, kc + 1);
            asm volatile("cp.async.commit_group;\n" ::: "memory");
            asm volatile("cp.async.wait_group 1;\n" ::: "memory");
        } else {
            asm volatile("cp.async.wait_group 0;\n" ::: "memory");
        }
        __syncthreads();                      // stage kc visible

        unsigned sbase = smem_u32 + (kc & 1) * STG_BYTES;
        #pragma unroll
        for (int ks = 0; ks < 2; ++ks) {
            const unsigned kbB = ks * 32;     // 16 bf16 = 32 bytes
            unsigned ah[8], al[8];
            ldsm4(ah[0], ah[1], ah[2], ah[3], sbase + aoff0 + kbB);
            ldsm4(ah[4], ah[5], ah[6], ah[7], sbase + aoff1 + kbB);
            ldsm4(al[0], al[1], al[2], al[3], sbase + ARR_BYTES + aoff0 + kbB);
            ldsm4(al[4], al[5], al[6], al[7], sbase + ARR_BYTES + aoff1 + kbB);
            #pragma unroll
            for (int p = 0; p < 4; ++p) {
                unsigned bh4[4], bl4[4];
                ldsm4(bh4[0], bh4[1], bh4[2], bh4[3], sbase + 2 * ARR_BYTES + boff[p] + kbB);
                ldsm4(bl4[0], bl4[1], bl4[2], bl4[3], sbase + 3 * ARR_BYTES + boff[p] + kbB);
                #pragma unroll
                for (int q = 0; q < 2; ++q) {
                    const int nt = p * 2 + q;
                    #pragma unroll
                    for (int mt = 0; mt < 2; ++mt) {
                        mma_bf16(acc[mt][nt], &ah[mt * 4], &bh4[q * 2]);  // hi*hi
                        mma_bf16(acc[mt][nt], &ah[mt * 4], &bl4[q * 2]);  // hi*lo
                        mma_bf16(acc[mt][nt], &al[mt * 4], &bh4[q * 2]);  // lo*hi
                    }
                }
            }
        }
        __syncthreads();                      // reads done before next overwrite
    }

    // ---- epilogue: bias + exact GELU ----
    #pragma unroll
    for (int mt = 0; mt < 2; ++mt)
        #pragma unroll
        for (int nt = 0; nt < 8; ++nt) {
            int c0 = wn * 64 + nt * 8 + tq * 2;
            float b0 = bias_s[c0], b1 = bias_s[c0 + 1];
            acc[mt][nt][0] = gelu_exact(acc[mt][nt][0] + b0);
            acc[mt][nt][1] = gelu_exact(acc[mt][nt][1] + b1);
            acc[mt][nt][2] = gelu_exact(acc[mt][nt][2] + b0);
            acc[mt][nt][3] = gelu_exact(acc[mt][nt][3] + b1);
        }

    // ---- store Y (pre-split bf16 hi/lo for layers 1-3; fp32 for layer 4) ----
    if (Yh) {
        #pragma unroll
        for (int mt = 0; mt < 2; ++mt)
            #pragma unroll
            for (int nt = 0; nt < 8; ++nt) {
                int r = rb * 128 + wm * 32 + mt * 16 + g8;
                int c = cb * 128 + wn * 64 + nt * 8 + tq * 2;
                __nv_bfloat16 h0,l0,h1,l1,h2,l2,h3,l3;
                split_bf16(acc[mt][nt][0], h0, l0);
                split_bf16(acc[mt][nt][1], h1, l1);
                split_bf16(acc[mt][nt][2], h2, l2);
                split_bf16(acc[mt][nt][3], h3, l3);
                __nv_bfloat162 p;
                p.x = h0; p.y = h1; *(__nv_bfloat162*)(Yh + (size_t)r * DIMD + c)       = p;
                p.x = l0; p.y = l1; *(__nv_bfloat162*)(Yl + (size_t)r * DIMD + c)       = p;
                p.x = h2; p.y = h3; *(__nv_bfloat162*)(Yh + (size_t)(r + 8) * DIMD + c) = p;
                p.x = l2; p.y = l3; *(__nv_bfloat162*)(Yl + (size_t)(r + 8) * DIMD + c) = p;
            }
    } else {
        #pragma unroll
        for (int mt = 0; mt < 2; ++mt)
            #pragma unroll
            for (int nt = 0; nt < 8; ++nt) {
                int r = rb * 128 + wm * 32 + mt * 16 + g8;
                int c = cb * 128 + wn * 64 + nt * 8 + tq * 2;
                *(float2*)&g_y4[(size_t)r * DIMD + c]       = make_float2(acc[mt][nt][0], acc[mt][nt][1]);
                *(float2*)&g_y4[(size_t)(r + 8) * DIMD + c] = make_float2(acc[mt][nt][2], acc[mt][nt][3]);
            }
    }

    // ---- count-weighted per-column BN stats (deterministic) ----
    if (do_stats) {
        const float w00 = cw_s[wm * 32 + g8];          // row (mt=0, base)
        const float w08 = cw_s[wm * 32 + 8 + g8];      // row (mt=0, +8)
        const float w10 = cw_s[wm * 32 + 16 + g8];     // row (mt=1, base)
        const float w18 = cw_s[wm * 32 + 24 + g8];     // row (mt=1, +8)
        #pragma unroll
        for (int nt = 0; nt < 8; ++nt) {
            float s0 = w00 * acc[0][nt][0] + w08 * acc[0][nt][2]
                     + w10 * acc[1][nt][0] + w18 * acc[1][nt][2];
            float s1 = w00 * acc[0][nt][1] + w08 * acc[0][nt][3]
                     + w10 * acc[1][nt][1] + w18 * acc[1][nt][3];
            float q0 = w00 * acc[0][nt][0] * acc[0][nt][0] + w08 * acc[0][nt][2] * acc[0][nt][2]
                     + w10 * acc[1][nt][0] * acc[1][nt][0] + w18 * acc[1][nt][2] * acc[1][nt][2];
            float q1 = w00 * acc[0][nt][1] * acc[0][nt][1] + w08 * acc[0][nt][3] * acc[0][nt][3]
                     + w10 * acc[1][nt][1] * acc[1][nt][1] + w18 * acc[1][nt][3] * acc[1][nt][3];
            #pragma unroll
            for (int off = 4; off < 32; off <<= 1) {   // reduce over row-groups (g8)
                s0 += __shfl_xor_sync(0xffffffffu, s0, off);
                s1 += __shfl_xor_sync(0xffffffffu, s1, off);
                q0 += __shfl_xor_sync(0xffffffffu, q0, off);
                q1 += __shfl_xor_sync(0xffffffffu, q1, off);
            }
            if (lane < 4) {
                int cl = wn * 64 + nt * 8 + lane * 2;  // lane==tq here
                csum[wm][cl] = s0; csum[wm][cl + 1] = s1;
                csq [wm][cl] = q0; csq [wm][cl + 1] = q1;
            }
        }
        __syncthreads();
        if (tid < 128) {
            float S = csum[0][tid] + csum[1][tid] + csum[2][tid] + csum[3][tid];
            float Q = csq [0][tid] + csq [1][tid] + csq [2][tid] + csq [3][tid];
            g_ps[(cb * 128 + tid) * NRBU + rb] = S;    // transposed for parallel fin
            g_pq[(cb * 128 + tid) * NRBU + rb] = Q;
        }
    }
}

// ---------------------------------------------------------------------------
extern "C" void kernel_launch(void* const* d_in, const int* in_sizes, int n_in,
                              void* d_out, int out_size) {
    (void)in_sizes; (void)n_in; (void)out_size;
    const int*   ids   = (const int*)  d_in[0];
    const float* table = (const float*)d_in[1];
    const float* W1 = (const float*)d_in[2],  *b1 = (const float*)d_in[3];
    const float* W2 = (const float*)d_in[4],  *b2 = (const float*)d_in[5];
    const float* W3 = (const float*)d_in[6],  *b3 = (const float*)d_in[7];
    const float* W4 = (const float*)d_in[8],  *b4 = (const float*)d_in[9];
    const float* g1 = (const float*)d_in[10], *be1 = (const float*)d_in[11];
    const float* g2 = (const float*)d_in[12], *be2 = (const float*)d_in[13];
    const float* g3 = (const float*)d_in[14], *be3 = (const float*)d_in[15];
    float* out = (float*)d_out;

    cudaFuncSetAttribute(gemm_kernel, cudaFuncAttributeMaxDynamicSharedMemorySize,
                         SMEM_BYTES);

    dim3 grid(2, NRBU), blk(256);

    winit_kernel<<<DIMD, DIMD>>>(W1);
    split_table_kernel<<<NU * 64 / 256, 256>>>(table);   // x0 = split(table), padded
    zero_cnt_kernel<<<(NU + 255) / 256, 256>>>();
    hist_kernel<<<NROWS / 256, 256>>>(ids);
    // layer 1: gelu(x0 @ W1 + b1) -> x1 (+weighted stats)
    gemm_kernel<<<grid, blk, SMEM_BYTES>>>(0, 1, 0, b1, -1, 1);
    fin_kernel<<<DIMD, 256>>>(g1, be1);
    wprep_kernel<<<DIMD, DIMD>>>(W2, b2, 1, 0);
    // layer 2: gelu(bn1(x1) @ W2 + b2) -> x2 (+weighted stats)
    gemm_kernel<<<grid, blk, SMEM_BYTES>>>(1, 2, 1, nullptr, 0, 1);
    fin_kernel<<<DIMD, 256>>>(g2, be2);
    wprep_kernel<<<DIMD, DIMD>>>(W3, b3, 2, 1);
    // layer 3: -> x1 (+weighted stats)
    gemm_kernel<<<grid, blk, SMEM_BYTES>>>(2, 1, 2, nullptr, 1, 1);
    fin_kernel<<<DIMD, 256>>>(g3, be3);
    wprep_kernel<<<DIMD, DIMD>>>(W4, b4, 3, 2);
    // layer 4: -> y4 fp32 (no stats)
    gemm_kernel<<<grid, blk, SMEM_BYTES>>>(1, 0, 3, nullptr, 2, 0);
    // batch materialization: out[b,c] = y4[ids[b,c]]
    gather_out_kernel<<<2048, 256>>>(ids, out);
}

// round 17
// speedup vs baseline: 2.0087x; 1.0066x over previous
#include <cuda_runtime.h>
#include <cuda_bf16.h>
#include <cstdint>

// ---------------------------------------------------------------------------
// StatePerturbationEncoder: gather -> [GEMM + GELU + BN]x3 -> GEMM + GELU
// R16: finer GEMM tiles (128x64, 128 threads, ~3 CTA/SM) to kill the wave-
// quantization tail seen at (2,157)x256t. Dedup by pert id (20096 unique rows,
// count-weighted BN stats), BN folded into next layer's weights, split-bf16
// (hi/lo) mma.sync 3-term product, 2-stage cp.async + ldmatrix mainloop.
// ---------------------------------------------------------------------------

#define NROWS 32768      // B*C (real batch)
#define NPERT 20000
#define NU    20096      // padded unique rows (157 * 128)
#define NRBU  157        // row blocks over unique rows
#define DIMD  256
#define EPSF  1e-5f

#define TILE_K    32
#define LDS_STRIDE 40                            // 32 + 8 pad; LDSM conflict-free
#define ARR_A_BYTES (128 * LDS_STRIDE * 2)       // 10240
#define ARR_B_BYTES (64  * LDS_STRIDE * 2)       // 5120
#define STG_BYTES (2 * ARR_A_BYTES + 2 * ARR_B_BYTES)  // 30720 (Ah|Al|Bh|Bl)
#define SMEM_BYTES (2 * STG_BYTES)               // 61440 -> ~3 CTAs/SM

// ----- scratch (static device globals; allocation-free at runtime) ---------
__device__ __align__(256) static __nv_bfloat16 g_x0h[NU*DIMD], g_x0l[NU*DIMD];
__device__ __align__(256) static __nv_bfloat16 g_x1h[NU*DIMD], g_x1l[NU*DIMD];
__device__ __align__(256) static __nv_bfloat16 g_x2h[NU*DIMD], g_x2l[NU*DIMD];
__device__ __align__(256) static float g_y4[NU*DIMD];      // final fp32 (pre-gather)
__device__ __align__(256) static int   g_cnt[NU];          // pert occurrence counts
__device__ __align__(256) static float g_ps[DIMD * NRBU];  // TRANSPOSED: [col][rb]
__device__ __align__(256) static float g_pq[DIMD * NRBU];
__device__ __align__(256) static __nv_bfloat16 g_w1h[DIMD*DIMD], g_w1l[DIMD*DIMD];
__device__ __align__(256) static __nv_bfloat16 g_w2h[DIMD*DIMD], g_w2l[DIMD*DIMD];
__device__ __align__(256) static __nv_bfloat16 g_w3h[DIMD*DIMD], g_w3l[DIMD*DIMD];
__device__ __align__(256) static __nv_bfloat16 g_w4h[DIMD*DIMD], g_w4l[DIMD*DIMD];
__device__ __align__(256) static float g_a[DIMD], g_c[DIMD];
__device__ __align__(256) static float g_bp[3][DIMD];      // folded biases, layers 2..4

// ----- helpers -------------------------------------------------------------
__device__ __forceinline__ void split_bf16(float x, __nv_bfloat16& h, __nv_bfloat16& l) {
    h = __float2bfloat16(x);
    l = __float2bfloat16(x - __bfloat162float(h));
}

__device__ __forceinline__ float gelu_exact(float x) {
    return x * normcdff(x);   // x * Phi(x), matches jax.nn.gelu(approximate=False)
}

__device__ __forceinline__ void mma_bf16(float* d, const unsigned* a, const unsigned* b) {
    asm volatile(
        "mma.sync.aligned.m16n8k16.row.col.f32.bf16.bf16.f32 "
        "{%0,%1,%2,%3}, {%4,%5,%6,%7}, {%8,%9}, {%0,%1,%2,%3};\n"
        : "+f"(d[0]), "+f"(d[1]), "+f"(d[2]), "+f"(d[3])
        : "r"(a[0]), "r"(a[1]), "r"(a[2]), "r"(a[3]), "r"(b[0]), "r"(b[1]));
}

__device__ __forceinline__ void ldsm4(unsigned& r0, unsigned& r1, unsigned& r2, unsigned& r3,
                                      unsigned addr) {
    asm volatile("ldmatrix.sync.aligned.m8n8.x4.shared.b16 {%0,%1,%2,%3}, [%4];\n"
        : "=r"(r0), "=r"(r1), "=r"(r2), "=r"(r3) : "r"(addr));
}

__device__ __forceinline__ void cp_async16(unsigned sdst, const __nv_bfloat16* gsrc) {
    asm volatile("cp.async.cg.shared.global [%0], [%1], 16;\n" :: "r"(sdst), "l"(gsrc) : "memory");
}

// ----- split table rows into x0 (unique-pert inputs; pad rows = 0) ----------
__global__ void split_table_kernel(const float* __restrict__ table) {
    int idx = blockIdx.x * blockDim.x + threadIdx.x;   // one float4 per thread
    int row = idx >> 6;                                // 64 float4 per row
    int seg = (idx & 63) << 2;
    float4 v = make_float4(0.f, 0.f, 0.f, 0.f);
    if (row < NPERT) v = *(const float4*)(table + (size_t)row * DIMD + seg);
    __nv_bfloat16 h0,l0,h1,l1,h2,l2,h3,l3;
    split_bf16(v.x, h0, l0); split_bf16(v.y, h1, l1);
    split_bf16(v.z, h2, l2); split_bf16(v.w, h3, l3);
    size_t off = (size_t)row * DIMD + seg;
    __nv_bfloat162 p;
    p.x = h0; p.y = h1; *(__nv_bfloat162*)(g_x0h + off)     = p;
    p.x = h2; p.y = h3; *(__nv_bfloat162*)(g_x0h + off + 2) = p;
    p.x = l0; p.y = l1; *(__nv_bfloat162*)(g_x0l + off)     = p;
    p.x = l2; p.y = l3; *(__nv_bfloat162*)(g_x0l + off + 2) = p;
}

// ----- histogram of pert ids (int atomics -> deterministic) ----------------
__global__ void zero_cnt_kernel() {
    int t = blockIdx.x * blockDim.x + threadIdx.x;
    if (t < NU) g_cnt[t] = 0;
}
__global__ void hist_kernel(const int* __restrict__ ids) {
    int t = blockIdx.x * blockDim.x + threadIdx.x;     // 32768 threads
    atomicAdd(&g_cnt[ids[t]], 1);
}

// ----- W1 transpose + split (layer-1 weights, no BN folding) ---------------
__global__ void winit_kernel(const float* __restrict__ W1) {
    int j = blockIdx.x, k = threadIdx.x;       // j = out col, k = in dim
    __nv_bfloat16 h, l;
    split_bf16(W1[k * DIMD + j], h, l);
    g_w1h[j * DIMD + k] = h;                   // stored [n][k] (transposed)
    g_w1l[j * DIMD + k] = l;
}

// ----- finalize BN stats (parallel): one block per column ------------------
__global__ void fin_kernel(const float* __restrict__ gam, const float* __restrict__ bet) {
    int j = blockIdx.x, t = threadIdx.x;
    int warp = t >> 5, lane = t & 31;
    float s = 0.f, q = 0.f;
    if (t < NRBU) {                            // 157 partial blocks
        s = g_ps[j * NRBU + t];
        q = g_pq[j * NRBU + t];
    }
    #pragma unroll
    for (int off = 16; off > 0; off >>= 1) {   // fixed order -> deterministic
        s += __shfl_xor_sync(0xffffffffu, s, off);
        q += __shfl_xor_sync(0xffffffffu, q, off);
    }
    __shared__ float ss[8], qq[8];
    if (lane == 0) { ss[warp] = s; qq[warp] = q; }
    __syncthreads();
    if (t == 0) {
        float S = ss[0] + ss[1] + ss[2] + ss[3] + ss[4] + ss[5] + ss[6] + ss[7];
        float Q = qq[0] + qq[1] + qq[2] + qq[3] + qq[4] + qq[5] + qq[6] + qq[7];
        const float invn = 1.0f / (float)NROWS;   // weighted stats over REAL batch
        float mu  = S * invn;
        float var = Q * invn - mu * mu;
        if (var < 0.f) var = 0.f;
        float ai  = gam[j] * rsqrtf(var + EPSF);
        g_a[j] = ai;
        g_c[j] = bet[j] - mu * ai;
    }
}

// ----- fold BN into next layer: W' = diag(a)W (transposed hi/lo), b' = b + c@W
__global__ void wprep_kernel(const float* __restrict__ W, const float* __restrict__ b,
                             int wsel, int bidx) {
    int j = blockIdx.x, k = threadIdx.x;
    int warp = k >> 5, lane = k & 31;
    float w  = W[k * DIMD + j];
    float wp = g_a[k] * w;
    __nv_bfloat16 h, l;
    split_bf16(wp, h, l);
    __nv_bfloat16 *Wh, *Wl;
    switch (wsel) {
        case 1:  Wh = g_w2h; Wl = g_w2l; break;
        case 2:  Wh = g_w3h; Wl = g_w3l; break;
        default: Wh = g_w4h; Wl = g_w4l; break;
    }
    Wh[j * DIMD + k] = h;
    Wl[j * DIMD + k] = l;

    float v = g_c[k] * w;
    #pragma unroll
    for (int off = 16; off > 0; off >>= 1)
        v += __shfl_xor_sync(0xffffffffu, v, off);
    __shared__ float r8[8];
    if (lane == 0) r8[warp] = v;
    __syncthreads();
    if (k == 0) {
        float R = r8[0] + r8[1] + r8[2] + r8[3] + r8[4] + r8[5] + r8[6] + r8[7];
        g_bp[bidx][j] = b[j] + R;
    }
}

// ----- final gather: out[b,c] = y4[ids[b,c]] (fp32) -------------------------
__global__ void gather_out_kernel(const int* __restrict__ ids, float* __restrict__ out) {
    int t = blockIdx.x * blockDim.x + threadIdx.x;     // 524288 threads
    #pragma unroll
    for (int i = 0; i < 4; ++i) {
        int c   = t + (i << 19);                       // float4 chunk id
        int row = c >> 6;
        int seg = (c & 63) << 2;
        float4 v = *(const float4*)(g_y4 + (size_t)ids[row] * DIMD + seg);
        *(float4*)(out + (size_t)row * DIMD + seg) = v;
    }
}

// ----- fused GEMM over unique rows: Y = gelu(X @ W'^T(hi/lo) + bias) -------
// block tile 128x64, K-chunks of 32, 4 warps (all in M), warp tile 32x64
// 2-stage cp.async pipeline, ldmatrix, ~3 CTAs/SM; count-weighted BN stats.
__global__ __launch_bounds__(128, 3)
void gemm_kernel(int xsel, int ysel,
                 int wsel, const float* __restrict__ bias_ext, int bidx,
                 int do_stats) {
    const __nv_bfloat16 *Xh, *Xl;
    if      (xsel == 0) { Xh = g_x0h; Xl = g_x0l; }
    else if (xsel == 1) { Xh = g_x1h; Xl = g_x1l; }
    else                { Xh = g_x2h; Xl = g_x2l; }
    __nv_bfloat16 *Yh = nullptr, *Yl = nullptr;
    if      (ysel == 1) { Yh = g_x1h; Yl = g_x1l; }
    else if (ysel == 2) { Yh = g_x2h; Yl = g_x2l; }
    const __nv_bfloat16 *Wh, *Wl;
    switch (wsel) {
        case 0:  Wh = g_w1h; Wl = g_w1l; break;
        case 1:  Wh = g_w2h; Wl = g_w2l; break;
        case 2:  Wh = g_w3h; Wl = g_w3l; break;
        default: Wh = g_w4h; Wl = g_w4l; break;
    }
    const float* bias = (bidx >= 0) ? g_bp[bidx] : bias_ext;

    extern __shared__ __align__(16) __nv_bfloat16 smem[];   // [2][Ah|Al|Bh|Bl]
    __shared__ float bias_s[64];
    __shared__ float cw_s[128];
    __shared__ float csum[4][64], csq[4][64];

    const int tid  = threadIdx.x;
    const int rb   = blockIdx.y, cb = blockIdx.x;
    const int warp = tid >> 5, lane = tid & 31;
    const int wm   = warp;                     // all 4 warps stacked in M
    const int g8   = lane >> 2, tq  = lane & 3;

    if (tid < 64) bias_s[tid] = bias[cb * 64 + tid];
    cw_s[tid] = (float)g_cnt[rb * 128 + tid];  // stats weights (128 rows)

    const __nv_bfloat16* Xhb = Xh + (size_t)(rb * 128) * DIMD;
    const __nv_bfloat16* Xlb = Xl + (size_t)(rb * 128) * DIMD;
    const __nv_bfloat16* Whb = Wh + (size_t)(cb * 64) * DIMD;
    const __nv_bfloat16* Wlb = Wl + (size_t)(cb * 64) * DIMD;

    const unsigned smem_u32 = (unsigned)__cvta_generic_to_shared(smem);

    // cp.async geometry: 16B segs; A: 512 chunks (4/thread/array), B: 256 (2/thread)
    auto load_stage = [&](int st, int kc) {
        unsigned base = smem_u32 + st * STG_BYTES;
        const int k0 = kc * TILE_K;
        #pragma unroll
        for (int i = 0; i < 4; ++i) {          // A hi/lo: 128 rows x 4 segs
            int idx = tid + i * 128, row = idx >> 2, sg = idx & 3;
            unsigned d = base + (row * LDS_STRIDE + sg * 8) * 2;
            const int koff = k0 + sg * 8;
            cp_async16(d,               Xhb + (size_t)row * DIMD + koff);
            cp_async16(d + ARR_A_BYTES, Xlb + (size_t)row * DIMD + koff);
        }
        #pragma unroll
        for (int i = 0; i < 2; ++i) {          // B hi/lo: 64 rows x 4 segs
            int idx = tid + i * 128, row = idx >> 2, sg = idx & 3;
            unsigned d = base + 2 * ARR_A_BYTES + (row * LDS_STRIDE + sg * 8) * 2;
            const int koff = k0 + sg * 8;
            cp_async16(d,               Whb + (size_t)row * DIMD + koff);
            cp_async16(d + ARR_B_BYTES, Wlb + (size_t)row * DIMD + koff);
        }
    };

    // ldmatrix per-lane byte offsets (within one array of a stage)
    const int lr = lane & 7, m8 = lane >> 3;
    const int arow = (m8 & 1) * 8 + lr;        // mats: (r,kb)(r+8,kb)(r,kb+8)(r+8,kb+8)
    const int acolB = (m8 >> 1) * 16;
    const int brow = (m8 >> 1) * 8 + lr;       // mats: (nt0,kb)(nt0,kb+8)(nt1,kb)(nt1,kb+8)
    const int bcolB = (m8 & 1) * 16;
    const unsigned aoff0 = (unsigned)((wm * 32 + arow) * LDS_STRIDE * 2 + acolB);
    const unsigned aoff1 = aoff0 + 16 * LDS_STRIDE * 2;
    unsigned boff[4];
    #pragma unroll
    for (int p = 0; p < 4; ++p)
        boff[p] = (unsigned)(((p * 16 + brow) * LDS_STRIDE) * 2 + bcolB);

    float acc[2][8][4];
    #pragma unroll
    for (int mt = 0; mt < 2; ++mt)
        #pragma unroll
        for (int nt = 0; nt < 8; ++nt)
            #pragma unroll
            for (int e = 0; e < 4; ++e) acc[mt][nt][e] = 0.f;

    load_stage(0, 0);
    asm volatile("cp.async.commit_group;\n" ::: "memory");

    for (int kc = 0; kc < 8; ++kc) {
        if (kc < 7) {
            load_stage((kc + 1) & 1, kc + 1);
            asm volatile("cp.async.commit_group;\n" ::: "memory");
            asm volatile("cp.async.wait_group 1;\n" ::: "memory");
        } else {
            asm volatile("cp.async.wait_group 0;\n" ::: "memory");
        }
        __syncthreads();                      // stage kc visible

        unsigned sbase = smem_u32 + (kc & 1) * STG_BYTES;
        #pragma unroll
        for (int ks = 0; ks < 2; ++ks) {
            const unsigned kbB = ks * 32;     // 16 bf16 = 32 bytes
            unsigned ah[8], al[8];
            ldsm4(ah[0], ah[1], ah[2], ah[3], sbase + aoff0 + kbB);
            ldsm4(ah[4], ah[5], ah[6], ah[7], sbase + aoff1 + kbB);
            ldsm4(al[0], al[1], al[2], al[3], sbase + ARR_A_BYTES + aoff0 + kbB);
            ldsm4(al[4], al[5], al[6], al[7], sbase + ARR_A_BYTES + aoff1 + kbB);
            #pragma unroll
            for (int p = 0; p < 4; ++p) {
                unsigned bh4[4], bl4[4];
                ldsm4(bh4[0], bh4[1], bh4[2], bh4[3],
                      sbase + 2 * ARR_A_BYTES + boff[p] + kbB);
                ldsm4(bl4[0], bl4[1], bl4[2], bl4[3],
                      sbase + 2 * ARR_A_BYTES + ARR_B_BYTES + boff[p] + kbB);
                #pragma unroll
                for (int q = 0; q < 2; ++q) {
                    const int nt = p * 2 + q;
                    #pragma unroll
                    for (int mt = 0; mt < 2; ++mt) {
                        mma_bf16(acc[mt][nt], &ah[mt * 4], &bh4[q * 2]);  // hi*hi
                        mma_bf16(acc[mt][nt], &ah[mt * 4], &bl4[q * 2]);  // hi*lo
                        mma_bf16(acc[mt][nt], &al[mt * 4], &bh4[q * 2]);  // lo*hi
                    }
                }
            }
        }
        __syncthreads();                      // reads done before next overwrite
    }

    // ---- epilogue: bias + exact GELU ----
    #pragma unroll
    for (int mt = 0; mt < 2; ++mt)
        #pragma unroll
        for (int nt = 0; nt < 8; ++nt) {
            int c0 = nt * 8 + tq * 2;
            float b0 = bias_s[c0], b1 = bias_s[c0 + 1];
            acc[mt][nt][0] = gelu_exact(acc[mt][nt][0] + b0);
            acc[mt][nt][1] = gelu_exact(acc[mt][nt][1] + b1);
            acc[mt][nt][2] = gelu_exact(acc[mt][nt][2] + b0);
            acc[mt][nt][3] = gelu_exact(acc[mt][nt][3] + b1);
        }

    // ---- store Y (pre-split bf16 hi/lo for layers 1-3; fp32 for layer 4) ----
    if (Yh) {
        #pragma unroll
        for (int mt = 0; mt < 2; ++mt)
            #pragma unroll
            for (int nt = 0; nt < 8; ++nt) {
                int r = rb * 128 + wm * 32 + mt * 16 + g8;
                int c = cb * 64 + nt * 8 + tq * 2;
                __nv_bfloat16 h0,l0,h1,l1,h2,l2,h3,l3;
                split_bf16(acc[mt][nt][0], h0, l0);
                split_bf16(acc[mt][nt][1], h1, l1);
                split_bf16(acc[mt][nt][2], h2, l2);
                split_bf16(acc[mt][nt][3], h3, l3);
                __nv_bfloat162 p;
                p.x = h0; p.y = h1; *(__nv_bfloat162*)(Yh + (size_t)r * DIMD + c)       = p;
                p.x = l0; p.y = l1; *(__nv_bfloat162*)(Yl + (size_t)r * DIMD + c)       = p;
                p.x = h2; p.y = h3; *(__nv_bfloat162*)(Yh + (size_t)(r + 8) * DIMD + c) = p;
                p.x = l2; p.y = l3; *(__nv_bfloat162*)(Yl + (size_t)(r + 8) * DIMD + c) = p;
            }
    } else {
        #pragma unroll
        for (int mt = 0; mt < 2; ++mt)
            #pragma unroll
            for (int nt = 0; nt < 8; ++nt) {
                int r = rb * 128 + wm * 32 + mt * 16 + g8;
                int c = cb * 64 + nt * 8 + tq * 2;
                *(float2*)&g_y4[(size_t)r * DIMD + c]       = make_float2(acc[mt][nt][0], acc[mt][nt][1]);
                *(float2*)&g_y4[(size_t)(r + 8) * DIMD + c] = make_float2(acc[mt][nt][2], acc[mt][nt][3]);
            }
    }

    // ---- count-weighted per-column BN stats (deterministic) ----
    if (do_stats) {
        const float w00 = cw_s[wm * 32 + g8];          // row (mt=0, base)
        const float w08 = cw_s[wm * 32 + 8 + g8];      // row (mt=0, +8)
        const float w10 = cw_s[wm * 32 + 16 + g8];     // row (mt=1, base)
        const float w18 = cw_s[wm * 32 + 24 + g8];     // row (mt=1, +8)
        #pragma unroll
        for (int nt = 0; nt < 8; ++nt) {
            float s0 = w00 * acc[0][nt][0] + w08 * acc[0][nt][2]
                     + w10 * acc[1][nt][0] + w18 * acc[1][nt][2];
            float s1 = w00 * acc[0][nt][1] + w08 * acc[0][nt][3]
                     + w10 * acc[1][nt][1] + w18 * acc[1][nt][3];
            float q0 = w00 * acc[0][nt][0] * acc[0][nt][0] + w08 * acc[0][nt][2] * acc[0][nt][2]
                     + w10 * acc[1][nt][0] * acc[1][nt][0] + w18 * acc[1][nt][2] * acc[1][nt][2];
            float q1 = w00 * acc[0][nt][1] * acc[0][nt][1] + w08 * acc[0][nt][3] * acc[0][nt][3]
                     + w10 * acc[1][nt][1] * acc[1][nt][1] + w18 * acc[1][nt][3] * acc[1][nt][3];
            #pragma unroll
            for (int off = 4; off < 32; off <<= 1) {   // reduce over row-groups (g8)
                s0 += __shfl_xor_sync(0xffffffffu, s0, off);
                s1 += __shfl_xor_sync(0xffffffffu, s1, off);
                q0 += __shfl_xor_sync(0xffffffffu, q0, off);
                q1 += __shfl_xor_sync(0xffffffffu, q1, off);
            }
            if (lane < 4) {
                int cl = nt * 8 + lane * 2;            // lane==tq here
                csum[wm][cl] = s0; csum[wm][cl + 1] = s1;
                csq [wm][cl] = q0; csq [wm][cl + 1] = q1;
            }
        }
        __syncthreads();
        if (tid < 64) {
            float S = csum[0][tid] + csum[1][tid] + csum[2][tid] + csum[3][tid];
            float Q = csq [0][tid] + csq [1][tid] + csq [2][tid] + csq [3][tid];
            g_ps[(cb * 64 + tid) * NRBU + rb] = S;     // transposed for parallel fin
            g_pq[(cb * 64 + tid) * NRBU + rb] = Q;
        }
    }
}

// ---------------------------------------------------------------------------
extern "C" void kernel_launch(void* const* d_in, const int* in_sizes, int n_in,
                              void* d_out, int out_size) {
    (void)in_sizes; (void)n_in; (void)out_size;
    const int*   ids   = (const int*)  d_in[0];
    const float* table = (const float*)d_in[1];
    const float* W1 = (const float*)d_in[2],  *b1 = (const float*)d_in[3];
    const float* W2 = (const float*)d_in[4],  *b2 = (const float*)d_in[5];
    const float* W3 = (const float*)d_in[6],  *b3 = (const float*)d_in[7];
    const float* W4 = (const float*)d_in[8],  *b4 = (const float*)d_in[9];
    const float* g1 = (const float*)d_in[10], *be1 = (const float*)d_in[11];
    const float* g2 = (const float*)d_in[12], *be2 = (const float*)d_in[13];
    const float* g3 = (const float*)d_in[14], *be3 = (const float*)d_in[15];
    float* out = (float*)d_out;

    cudaFuncSetAttribute(gemm_kernel, cudaFuncAttributeMaxDynamicSharedMemorySize,
                         SMEM_BYTES);

    dim3 grid(4, NRBU), blk(128);

    winit_kernel<<<DIMD, DIMD>>>(W1);
    split_table_kernel<<<NU * 64 / 256, 256>>>(table);   // x0 = split(table), padded
    zero_cnt_kernel<<<(NU + 255) / 256, 256>>>();
    hist_kernel<<<NROWS / 256, 256>>>(ids);
    // layer 1: gelu(x0 @ W1 + b1) -> x1 (+weighted stats)
    gemm_kernel<<<grid, blk, SMEM_BYTES>>>(0, 1, 0, b1, -1, 1);
    fin_kernel<<<DIMD, 256>>>(g1, be1);
    wprep_kernel<<<DIMD, DIMD>>>(W2, b2, 1, 0);
    // layer 2: gelu(bn1(x1) @ W2 + b2) -> x2 (+weighted stats)
    gemm_kernel<<<grid, blk, SMEM_BYTES>>>(1, 2, 1, nullptr, 0, 1);
    fin_kernel<<<DIMD, 256>>>(g2, be2);
    wprep_kernel<<<DIMD, DIMD>>>(W3, b3, 2, 1);
    // layer 3: -> x1 (+weighted stats)
    gemm_kernel<<<grid, blk, SMEM_BYTES>>>(2, 1, 2, nullptr, 1, 1);
    fin_kernel<<<DIMD, 256>>>(g3, be3);
    wprep_kernel<<<DIMD, DIMD>>>(W4, b4, 3, 2);
    // layer 4: -> y4 fp32 (no stats)
    gemm_kernel<<<grid, blk, SMEM_BYTES>>>(1, 0, 3, nullptr, 2, 0);
    // batch materialization: out[b,c] = y4[ids[b,c]]
    gather_out_kernel<<<2048, 256>>>(ids, out);
}